// round 7
// baseline (speedup 1.0000x reference)
#include <cuda_runtime.h>
#include <math.h>
#include <stdint.h>

// ---------------------------------------------------------------- constants
#define NROWS   9216      // B*R
#define K1      2816      // IMG+TAG
#define K2      3072      // padded (3016 -> 3072)
#define K2RAW   3016
#define N1      200       // POS_EMBED
#define N1P     256       // padded
#define N2      1024
#define BOXL    15
#define PEMB    200

#define BN      128
#define TBM     128
#define BK      64        // int8 K elements per stage (64B per row per split)
#define ROWB    80        // padded row stride bytes (64B data + 16B pad)
#define NSTG    5
#define T_A2    (TBM*ROWB)            // 10240
#define T_B1    (2*TBM*ROWB)          // 20480
#define T_B2    (2*TBM*ROWB+BN*ROWB)  // 30720
#define STAGE_B (2*(TBM+BN)*ROWB)     // 40960
#define SMEM_SZ (NSTG*STAGE_B)        // 204800

#define QINV    (1.0f/254.0f)

// ---------------------------------------------------------------- scratch
__device__ int8_t g_Xq1[(long)NROWS * K2];
__device__ int8_t g_Xq2[(long)NROWS * K2];
__device__ int8_t g_W2q1[(long)N2 * K2];
__device__ int8_t g_W2q2[(long)N2 * K2];
__device__ int8_t g_W1q1[(long)N1P * K1];
__device__ int8_t g_W1q2[(long)N1P * K1];
__device__ float g_sa[NROWS];
__device__ float g_sb1[N1P];
__device__ float g_sb2[N2];
__device__ float g_box[(long)NROWS * PEMB];
__device__ float g_region[(long)NROWS * N1];

// ---------------------------------------------------------------- utils
__device__ __forceinline__ uint32_t smem_u32(const void* p) {
    uint32_t a;
    asm("{ .reg .u64 t; cvta.to.shared.u64 t, %1; cvt.u32.u64 %0, t; }"
        : "=r"(a) : "l"(p));
    return a;
}
__device__ __forceinline__ void cp16(uint32_t dst, const void* src) {
    asm volatile("cp.async.cg.shared.global [%0], [%1], 16;" :: "r"(dst), "l"(src));
}
__device__ __forceinline__ void cp_commit() {
    asm volatile("cp.async.commit_group;" ::: "memory");
}
template<int N>
__device__ __forceinline__ void cp_wait() {
    asm volatile("cp.async.wait_group %0;" :: "n"(N) : "memory");
}
__device__ __forceinline__ void ldsm4(uint32_t* r, uint32_t addr) {
    asm volatile("ldmatrix.sync.aligned.m8n8.x4.shared.b16 {%0,%1,%2,%3}, [%4];"
                 : "=r"(r[0]), "=r"(r[1]), "=r"(r[2]), "=r"(r[3]) : "r"(addr));
}
__device__ __forceinline__ void imma16832(int* d, const uint32_t* a,
                                          uint32_t b0, uint32_t b1) {
    asm volatile(
        "mma.sync.aligned.m16n8k32.row.col.s32.s8.s8.s32 "
        "{%0,%1,%2,%3}, {%4,%5,%6,%7}, {%8,%9}, {%0,%1,%2,%3};"
        : "+r"(d[0]), "+r"(d[1]), "+r"(d[2]), "+r"(d[3])
        : "r"(a[0]), "r"(a[1]), "r"(a[2]), "r"(a[3]), "r"(b0), "r"(b1));
}

// ---------------------------------------------------------------- quant utils
__device__ __forceinline__ float block_amax(float m) {
    __shared__ float sh[8];
    int lane = threadIdx.x & 31, wid = threadIdx.x >> 5;
#pragma unroll
    for (int o = 16; o > 0; o >>= 1)
        m = fmaxf(m, __shfl_xor_sync(0xffffffffu, m, o));
    if (lane == 0) sh[wid] = m;
    __syncthreads();
    if (threadIdx.x == 0) {
        float r = sh[0];
        for (int i = 1; i < (int)(blockDim.x >> 5); i++) r = fmaxf(r, sh[i]);
        sh[0] = r;
    }
    __syncthreads();
    return sh[0];
}

__device__ __forceinline__ void quant_store16(const float* v, float inv,
                                              int8_t* q1p, int8_t* q2p) {
    signed char q1[16], q2[16];
#pragma unroll
    for (int i = 0; i < 16; i++) {
        float t = v[i] * inv;
        float a1 = rintf(t);
        q1[i] = (signed char)(int)a1;
        q2[i] = (signed char)(int)rintf((t - a1) * 254.f);
    }
    *reinterpret_cast<uint4*>(q1p) = *reinterpret_cast<const uint4*>(q1);
    *reinterpret_cast<uint4*>(q2p) = *reinterpret_cast<const uint4*>(q2);
}

// ---------------------------------------------------------------- X quant (pre: cols [0,2816))
__global__ void __launch_bounds__(192) quantX_pre(const float* __restrict__ images,
                                                  const float* __restrict__ tag) {
    int row = blockIdx.x, t = threadIdx.x;
    float v[16];
    if (t < 128) {
        const float4* p = reinterpret_cast<const float4*>(images + (long)row * 2048 + t * 16);
#pragma unroll
        for (int i = 0; i < 4; i++) *reinterpret_cast<float4*>(v + 4 * i) = p[i];
    } else if (t < 176) {
        const float4* p = reinterpret_cast<const float4*>(tag + (long)row * 768 + t * 16 - 2048);
#pragma unroll
        for (int i = 0; i < 4; i++) *reinterpret_cast<float4*>(v + 4 * i) = p[i];
    } else {
#pragma unroll
        for (int i = 0; i < 16; i++) v[i] = 0.f;
    }
    float m = 0.f;
#pragma unroll
    for (int i = 0; i < 16; i++) m = fmaxf(m, fabsf(v[i]));
    float amax = block_amax(m);
    if (t == 0) g_sa[row] = amax * (1.f / 127.f);
    float inv = amax > 0.f ? 127.f / amax : 0.f;
    if (t < 176)
        quant_store16(v, inv, g_Xq1 + (long)row * K2 + t * 16,
                              g_Xq2 + (long)row * K2 + t * 16);
}

// ---------------------------------------------------------------- X quant (full row, incl box_feat)
__global__ void __launch_bounds__(192) quantX_full(const float* __restrict__ images,
                                                   const float* __restrict__ tag) {
    int row = blockIdx.x, t = threadIdx.x;
    float v[16];
    if (t < 128) {
        const float4* p = reinterpret_cast<const float4*>(images + (long)row * 2048 + t * 16);
#pragma unroll
        for (int i = 0; i < 4; i++) *reinterpret_cast<float4*>(v + 4 * i) = p[i];
    } else if (t < 176) {
        const float4* p = reinterpret_cast<const float4*>(tag + (long)row * 768 + t * 16 - 2048);
#pragma unroll
        for (int i = 0; i < 4; i++) *reinterpret_cast<float4*>(v + 4 * i) = p[i];
    } else if (t < 188) {
        const float4* p = reinterpret_cast<const float4*>(g_box + (long)row * PEMB + t * 16 - 2816);
#pragma unroll
        for (int i = 0; i < 4; i++) *reinterpret_cast<float4*>(v + 4 * i) = p[i];
    } else if (t == 188) {
        const float4* p = reinterpret_cast<const float4*>(g_box + (long)row * PEMB + 192);
        *reinterpret_cast<float4*>(v)     = p[0];
        *reinterpret_cast<float4*>(v + 4) = p[1];
#pragma unroll
        for (int i = 8; i < 16; i++) v[i] = 0.f;
    } else {
#pragma unroll
        for (int i = 0; i < 16; i++) v[i] = 0.f;
    }
    float m = 0.f;
#pragma unroll
    for (int i = 0; i < 16; i++) m = fmaxf(m, fabsf(v[i]));
    float amax = block_amax(m);
    if (t == 0) g_sa[row] = amax * (1.f / 127.f);
    float inv = amax > 0.f ? 127.f / amax : 0.f;
    quant_store16(v, inv, g_Xq1 + (long)row * K2 + t * 16,
                          g_Xq2 + (long)row * K2 + t * 16);
}

// ---------------------------------------------------------------- W2 quant (permute img|box|tag -> img|tag|box|0)
__global__ void __launch_bounds__(192) quantW2(const float* __restrict__ fcW) {
    int row = blockIdx.x, t = threadIdx.x;
    const float* src = fcW + (long)row * K2RAW;
    float v[16];
    if (t < 128) {
        const float4* p = reinterpret_cast<const float4*>(src + t * 16);
#pragma unroll
        for (int i = 0; i < 4; i++) *reinterpret_cast<float4*>(v + 4 * i) = p[i];
    } else if (t < 176) {
        const float4* p = reinterpret_cast<const float4*>(src + t * 16 + 200);
#pragma unroll
        for (int i = 0; i < 4; i++) *reinterpret_cast<float4*>(v + 4 * i) = p[i];
    } else if (t < 188) {
        const float4* p = reinterpret_cast<const float4*>(src + t * 16 - 768);
#pragma unroll
        for (int i = 0; i < 4; i++) *reinterpret_cast<float4*>(v + 4 * i) = p[i];
    } else if (t == 188) {
        const float4* p = reinterpret_cast<const float4*>(src + 2240);
        *reinterpret_cast<float4*>(v)     = p[0];
        *reinterpret_cast<float4*>(v + 4) = p[1];
#pragma unroll
        for (int i = 8; i < 16; i++) v[i] = 0.f;
    } else {
#pragma unroll
        for (int i = 0; i < 16; i++) v[i] = 0.f;
    }
    float m = 0.f;
#pragma unroll
    for (int i = 0; i < 16; i++) m = fmaxf(m, fabsf(v[i]));
    float amax = block_amax(m);
    if (t == 0) g_sb2[row] = amax * (1.f / 127.f);
    float inv = amax > 0.f ? 127.f / amax : 0.f;
    quant_store16(v, inv, g_W2q1 + (long)row * K2 + t * 16,
                          g_W2q2 + (long)row * K2 + t * 16);
}

// ---------------------------------------------------------------- W1 quant (pad rows 200..255 = 0)
__global__ void __launch_bounds__(192) quantW1(const float* __restrict__ aW) {
    int row = blockIdx.x, t = threadIdx.x;
    float v[16];
    if (row < N1 && t < 176) {
        const float4* p = reinterpret_cast<const float4*>(aW + (long)row * K1 + t * 16);
#pragma unroll
        for (int i = 0; i < 4; i++) *reinterpret_cast<float4*>(v + 4 * i) = p[i];
    } else {
#pragma unroll
        for (int i = 0; i < 16; i++) v[i] = 0.f;
    }
    float m = 0.f;
#pragma unroll
    for (int i = 0; i < 16; i++) m = fmaxf(m, fabsf(v[i]));
    float amax = block_amax(m);
    if (t == 0) g_sb1[row] = amax * (1.f / 127.f);
    float inv = amax > 0.f ? 127.f / amax : 0.f;
    if (t < 176)
        quant_store16(v, inv, g_W1q1 + (long)row * K1 + t * 16,
                              g_W1q2 + (long)row * K1 + t * 16);
}

// ---------------------------------------------------------------- IMMA GEMM
// C[m][n] = sa[m]*sb[n]*(acc1 + acc2/254) + bias[n]
// acc1 = sum q1A*q1B, acc2 = sum (q1A*q2B + q2A*q1B). TBM=128, BN=128,
// 512 threads, warp grid 4x4, warp tile 32x32 (MT=2, NT=4, NP=2).
__global__ void __launch_bounds__(512, 1)
imma_gemm(const int8_t* __restrict__ A1, const int8_t* __restrict__ A2, int lda,
          const int8_t* __restrict__ B1, const int8_t* __restrict__ B2, int ldb,
          int K, const float* __restrict__ sa, const float* __restrict__ sb,
          const float* __restrict__ bias,
          float* __restrict__ C, int N, int ldc) {
    constexpr int MT = 2, NT = 4, NP = 2;
    extern __shared__ char smem[];
    const uint32_t sbse = smem_u32(smem);
    const int tid  = threadIdx.x;
    const int lane = tid & 31;
    const int wid  = tid >> 5;
    const int wm   = (wid & 3) * 32;
    const int wn   = (wid >> 2) * 32;
    const long m0  = (long)blockIdx.y * TBM;
    const long n0  = (long)blockIdx.x * BN;

    int acc1[MT][NT][4], acc2[MT][NT][4];
#pragma unroll
    for (int i = 0; i < MT; i++)
#pragma unroll
        for (int j = 0; j < NT; j++)
#pragma unroll
            for (int c = 0; c < 4; c++) { acc1[i][j][c] = 0; acc2[i][j][c] = 0; }

    uint32_t a_off[MT];
#pragma unroll
    for (int mt = 0; mt < MT; mt++)
        a_off[mt] = (uint32_t)(wm + mt * 16 + (lane & 15)) * ROWB + (lane >> 4) * 16;
    uint32_t b_off[NP];
#pragma unroll
    for (int np = 0; np < NP; np++)
        b_off[np] = T_B1
                  + (uint32_t)(wn + np * 16 + ((lane & 7) | ((lane >> 4) << 3))) * ROWB
                  + ((lane >> 3) & 1) * 16;

    const int arow = tid >> 2, aks = tid & 3;
    const uint32_t asw = (uint32_t)arow * ROWB + aks * 16;

    auto load_stage = [&](int buf, long kb) {
        uint32_t st = sbse + buf * STAGE_B;
        const long ga = (m0 + arow) * lda + kb + aks * 16;
        const long gb = (n0 + arow) * ldb + kb + aks * 16;
        cp16(st + asw,        A1 + ga);
        cp16(st + T_A2 + asw, A2 + ga);
        cp16(st + T_B1 + asw, B1 + gb);
        cp16(st + T_B2 + asw, B2 + gb);
    };

    const int S = K / BK;
#pragma unroll 1
    for (int p = 0; p < NSTG - 1; p++) {
        load_stage(p, (long)p * BK);
        cp_commit();
    }

#pragma unroll 1
    for (int s = 0; s < S; s++) {
        cp_wait<NSTG - 2>();
        __syncthreads();
        if (s + NSTG - 1 < S)
            load_stage((s + NSTG - 1) % NSTG, (long)(s + NSTG - 1) * BK);
        cp_commit();

        uint32_t st = sbse + (s % NSTG) * STAGE_B;
#pragma unroll
        for (int kk = 0; kk < 2; kk++) {
            uint32_t a1r[MT][4], a2r[MT][4];
            uint32_t b1r[NP][4], b2r[NP][4];
#pragma unroll
            for (int mt = 0; mt < MT; mt++) {
                ldsm4(a1r[mt], st + a_off[mt] + kk * 32);
                ldsm4(a2r[mt], st + T_A2 + a_off[mt] + kk * 32);
            }
#pragma unroll
            for (int np = 0; np < NP; np++) {
                ldsm4(b1r[np], st + b_off[np] + kk * 32);
                ldsm4(b2r[np], st + (T_B2 - T_B1) + b_off[np] + kk * 32);
            }
#pragma unroll
            for (int np = 0; np < NP; np++)
#pragma unroll
                for (int j = 0; j < 2; j++) {
                    int nt = np * 2 + j;
#pragma unroll
                    for (int mt = 0; mt < MT; mt++) {
                        imma16832(acc1[mt][nt], a1r[mt], b1r[np][2*j], b1r[np][2*j+1]);
                        imma16832(acc2[mt][nt], a1r[mt], b2r[np][2*j], b2r[np][2*j+1]);
                        imma16832(acc2[mt][nt], a2r[mt], b1r[np][2*j], b1r[np][2*j+1]);
                    }
                }
        }
    }

    // epilogue: f = sa*sb*(acc1 + acc2/254) + bias
    const int gr = lane >> 2;
    const int gc = (lane & 3) * 2;
#pragma unroll
    for (int mt = 0; mt < MT; mt++) {
        long m = m0 + wm + mt * 16 + gr;
        float sm0 = sa[m], sm8 = sa[m + 8];
#pragma unroll
        for (int nt = 0; nt < NT; nt++) {
            int n = (int)n0 + wn + nt * 8 + gc;
            if (n < N) {
                float sn0 = sb[n], sn1 = sb[n + 1];
                float b0 = bias ? bias[n] : 0.f;
                float b1 = bias ? bias[n + 1] : 0.f;
                float2 v0, v1;
                v0.x = ((float)acc1[mt][nt][0] + (float)acc2[mt][nt][0] * QINV) * (sm0 * sn0) + b0;
                v0.y = ((float)acc1[mt][nt][1] + (float)acc2[mt][nt][1] * QINV) * (sm0 * sn1) + b1;
                v1.x = ((float)acc1[mt][nt][2] + (float)acc2[mt][nt][2] * QINV) * (sm8 * sn0) + b0;
                v1.y = ((float)acc1[mt][nt][3] + (float)acc2[mt][nt][3] * QINV) * (sm8 * sn1) + b1;
                *reinterpret_cast<float2*>(C + m * ldc + n) = v0;
                *reinterpret_cast<float2*>(C + (m + 8) * ldc + n) = v1;
            }
        }
    }
}

// ---------------------------------------------------------------- attention
__global__ void attn_kernel(const float* __restrict__ boxes,
                            const float* __restrict__ pos_emb) {
    int row  = blockIdx.x * 8 + (threadIdx.x >> 5);
    int lane = threadIdx.x & 31;
    if (row >= NROWS) return;

    const float* region = g_region + (long)row * N1;
    float reg[7];
#pragma unroll
    for (int i = 0; i < 7; i++) {
        int e = lane + 32 * i;
        reg[i] = (e < PEMB) ? region[e] : 0.f;
    }

    const float* brow = boxes + (long)row * (2 * BOXL);
    int   idx[BOXL];
    float w[BOXL], sc[BOXL];
#pragma unroll
    for (int k = 0; k < BOXL; k++) {
        idx[k] = (int)brow[k];
        w[k]   = brow[BOXL + k];
    }

#pragma unroll
    for (int k = 0; k < BOXL; k++) {
        const float* pe = pos_emb + (long)idx[k] * PEMB;
        float p = 0.f;
#pragma unroll
        for (int i = 0; i < 7; i++) {
            int e = lane + 32 * i;
            if (e < PEMB) p += reg[i] * pe[e];
        }
#pragma unroll
        for (int o = 16; o > 0; o >>= 1)
            p += __shfl_xor_sync(0xffffffffu, p, o);
        sc[k] = tanhf(p);
    }

    float mx = -1e30f;
#pragma unroll
    for (int k = 0; k < BOXL; k++) mx = fmaxf(mx, sc[k]);
    float ssum = 0.f;
#pragma unroll
    for (int k = 0; k < BOXL; k++) { sc[k] = expf(sc[k] - mx); ssum += sc[k]; }
    float tot = 0.f;
#pragma unroll
    for (int k = 0; k < BOXL; k++) { sc[k] = sc[k] / ssum * w[k]; tot += sc[k]; }
    float inv = 1.f / (tot + 1e-6f);

#pragma unroll
    for (int i = 0; i < 7; i++) {
        int e = lane + 32 * i;
        if (e < PEMB) {
            float f = 0.f;
#pragma unroll
            for (int k = 0; k < BOXL; k++)
                f += sc[k] * pos_emb[(long)idx[k] * PEMB + e];
            g_box[(long)row * PEMB + e] = f * inv;
        }
    }
}

// ---------------------------------------------------------------- L2 norm
__global__ void norm_kernel(float* __restrict__ out) {
    int row  = blockIdx.x * 8 + (threadIdx.x >> 5);
    int lane = threadIdx.x & 31;
    if (row >= NROWS) return;

    float4* p = reinterpret_cast<float4*>(out + (long)row * N2);
    float4 v[8];
    float s = 0.f;
#pragma unroll
    for (int i = 0; i < 8; i++) {
        v[i] = p[lane + 32 * i];
        s += v[i].x * v[i].x + v[i].y * v[i].y + v[i].z * v[i].z + v[i].w * v[i].w;
    }
#pragma unroll
    for (int o = 16; o > 0; o >>= 1)
        s += __shfl_xor_sync(0xffffffffu, s, o);
    float scale = 1.f / (sqrtf(s) + 1e-8f);
#pragma unroll
    for (int i = 0; i < 8; i++) {
        v[i].x *= scale; v[i].y *= scale; v[i].z *= scale; v[i].w *= scale;
        p[lane + 32 * i] = v[i];
    }
}

// ---------------------------------------------------------------- launch
extern "C" void kernel_launch(void* const* d_in, const int* in_sizes, int n_in,
                              void* d_out, int out_size) {
    const float* images  = (const float*)d_in[0];
    const float* tag     = (const float*)d_in[1];
    const float* boxes   = (const float*)d_in[2];
    const float* pos_emb = (const float*)d_in[3];
    const float* attn_W  = (const float*)d_in[4];
    const float* fc_W    = (const float*)d_in[5];
    const float* fc_b    = (const float*)d_in[6];
    float* out = (float*)d_out;

    cudaFuncSetAttribute(imma_gemm, cudaFuncAttributeMaxDynamicSharedMemorySize,
                         SMEM_SZ);

    void *xq1, *xq2, *w2q1, *w2q2, *w1q1, *w1q2, *rg, *sa, *sb1, *sb2;
    cudaGetSymbolAddress(&xq1, g_Xq1);   cudaGetSymbolAddress(&xq2, g_Xq2);
    cudaGetSymbolAddress(&w2q1, g_W2q1); cudaGetSymbolAddress(&w2q2, g_W2q2);
    cudaGetSymbolAddress(&w1q1, g_W1q1); cudaGetSymbolAddress(&w1q2, g_W1q2);
    cudaGetSymbolAddress(&rg, g_region);
    cudaGetSymbolAddress(&sa, g_sa);
    cudaGetSymbolAddress(&sb1, g_sb1);
    cudaGetSymbolAddress(&sb2, g_sb2);

    // 1. quantize weights (once per launch) + X cols [0,2816)
    quantW1<<<N1P, 192>>>(attn_W);
    quantW2<<<N2, 192>>>(fc_W);
    quantX_pre<<<NROWS, 192>>>(images, tag);

    // 2. GEMM1: region = X[:, :2816] @ attn_W^T   (144 CTAs)
    {
        dim3 grid(N1P / BN, NROWS / TBM);
        imma_gemm<<<grid, 512, SMEM_SZ>>>(
            (const int8_t*)xq1, (const int8_t*)xq2, K2,
            (const int8_t*)w1q1, (const int8_t*)w1q2, K1,
            K1, (const float*)sa, (const float*)sb1, nullptr,
            (float*)rg, N1, N1);
    }

    // 3. attention -> box_feat (fp32) into g_box
    attn_kernel<<<NROWS / 8, 256>>>(boxes, pos_emb);

    // 4. re-quantize full rows (scale now includes box_feat)
    quantX_full<<<NROWS, 192>>>(images, tag);

    // 5. GEMM2: out = X @ W2^T + fc_b   (576 CTAs)
    {
        dim3 grid(N2 / BN, NROWS / TBM);
        imma_gemm<<<grid, 512, SMEM_SZ>>>(
            (const int8_t*)xq1, (const int8_t*)xq2, K2,
            (const int8_t*)w2q1, (const int8_t*)w2q2, K2,
            K2, (const float*)sa, (const float*)sb2, fc_b,
            out, N2, N2);
    }

    // 6. L2 normalize
    norm_kernel<<<NROWS / 8, 256>>>(out);
}

// round 8
// speedup vs baseline: 2.3064x; 2.3064x over previous
#include <cuda_runtime.h>
#include <cuda_bf16.h>
#include <math.h>
#include <stdint.h>

// ---------------------------------------------------------------- constants
#define NROWS   9216      // B*R
#define K1      2816      // IMG+TAG
#define K2      3072      // padded (3016 -> 3072)
#define K2RAW   3016
#define N1      200       // POS_EMBED
#define N1P     256       // padded
#define N2      1024
#define BOXL    15
#define PEMB    200

#define TBM     128
#define BN      128
#define BK      32
#define NSTG    5
#define T_AL    8192                 // TBM*64
#define T_BH    16384
#define T_BL    24576
#define STAGE_B 32768                // 2*(TBM+BN)*64
#define SMEM_SZ (NSTG*STAGE_B)       // 163840

// ---------------------------------------------------------------- scratch
__device__ __nv_bfloat16 g_Xh[(long)NROWS * K2];
__device__ __nv_bfloat16 g_Xl[(long)NROWS * K2];
__device__ __nv_bfloat16 g_W2h[(long)N2 * K2];
__device__ __nv_bfloat16 g_W2l[(long)N2 * K2];
__device__ __nv_bfloat16 g_W1h[(long)N1P * K1];
__device__ __nv_bfloat16 g_W1l[(long)N1P * K1];
__device__ float g_region[(long)NROWS * N1];

// ---------------------------------------------------------------- utils
__device__ __forceinline__ uint32_t smem_u32(const void* p) {
    uint32_t a;
    asm("{ .reg .u64 t; cvta.to.shared.u64 t, %1; cvt.u32.u64 %0, t; }"
        : "=r"(a) : "l"(p));
    return a;
}
// Swizzle<2,4,3>: 64B rows, chunk(16B) ^= (row>>1)&3  — conflict-free ldsm/STS
__device__ __forceinline__ uint32_t swz64(uint32_t row, uint32_t chunk) {
    return row * 64 + ((chunk ^ ((row >> 1) & 3)) << 4);
}
__device__ __forceinline__ void cp16(uint32_t dst, const void* src) {
    asm volatile("cp.async.cg.shared.global [%0], [%1], 16;" :: "r"(dst), "l"(src));
}
__device__ __forceinline__ void cp_commit() {
    asm volatile("cp.async.commit_group;" ::: "memory");
}
template<int N>
__device__ __forceinline__ void cp_wait() {
    asm volatile("cp.async.wait_group %0;" :: "n"(N) : "memory");
}
__device__ __forceinline__ void ldsm4(uint32_t* r, uint32_t addr) {
    asm volatile("ldmatrix.sync.aligned.m8n8.x4.shared.b16 {%0,%1,%2,%3}, [%4];"
                 : "=r"(r[0]), "=r"(r[1]), "=r"(r[2]), "=r"(r[3]) : "r"(addr));
}
__device__ __forceinline__ void mma16816(float* d, const uint32_t* a,
                                         uint32_t b0, uint32_t b1) {
    asm volatile(
        "mma.sync.aligned.m16n8k16.row.col.f32.bf16.bf16.f32 "
        "{%0,%1,%2,%3}, {%4,%5,%6,%7}, {%8,%9}, {%0,%1,%2,%3};"
        : "+f"(d[0]), "+f"(d[1]), "+f"(d[2]), "+f"(d[3])
        : "r"(a[0]), "r"(a[1]), "r"(a[2]), "r"(a[3]), "r"(b0), "r"(b1));
}
__device__ __forceinline__ void split2(float v, __nv_bfloat16& h, __nv_bfloat16& l) {
    h = __float2bfloat16(v);
    l = __float2bfloat16(v - __bfloat162float(h));
}

// ---------------------------------------------------------------- conversions
__global__ void convX_kernel(const float* __restrict__ images,
                             const float* __restrict__ tag) {
    int i = blockIdx.x * blockDim.x + threadIdx.x;
    if (i >= NROWS * 768) return;
    int row = i / 768;
    int c4  = i - row * 768;
    float4 v;
    if (c4 < 512)      v = reinterpret_cast<const float4*>(images)[(long)row * 512 + c4];
    else if (c4 < 704) v = reinterpret_cast<const float4*>(tag)[(long)row * 192 + (c4 - 512)];
    else if (c4 < 754) return;   // box_feat region: written by attn kernel
    else               v = make_float4(0.f, 0.f, 0.f, 0.f);
    long base = (long)row * K2 + c4 * 4;
    __nv_bfloat16 h[4], l[4];
    split2(v.x, h[0], l[0]); split2(v.y, h[1], l[1]);
    split2(v.z, h[2], l[2]); split2(v.w, h[3], l[3]);
    *reinterpret_cast<uint2*>(g_Xh + base) = *reinterpret_cast<uint2*>(h);
    *reinterpret_cast<uint2*>(g_Xl + base) = *reinterpret_cast<uint2*>(l);
}

__global__ void convW2_kernel(const float* __restrict__ fcW) {
    int i = blockIdx.x * blockDim.x + threadIdx.x;
    if (i >= N2 * K2) return;
    int n = i / K2;
    int k = i - n * K2;
    float v;
    if (k < 2048)      v = fcW[(long)n * K2RAW + k];
    else if (k < 2816) v = fcW[(long)n * K2RAW + k + 200];
    else if (k < 3016) v = fcW[(long)n * K2RAW + k - 768];
    else               v = 0.f;
    __nv_bfloat16 h, l; split2(v, h, l);
    g_W2h[i] = h; g_W2l[i] = l;
}

__global__ void convW1_kernel(const float* __restrict__ aW) {
    int i = blockIdx.x * blockDim.x + threadIdx.x;
    if (i >= N1P * K1) return;
    int n = i / K1;
    int k = i - n * K1;
    float v = (n < N1) ? aW[(long)n * K1 + k] : 0.f;
    __nv_bfloat16 h, l; split2(v, h, l);
    g_W1h[i] = h; g_W1l[i] = l;
}

// ---------------------------------------------------------------- HMMA GEMM
// C[M,N] = A[M,K]*B[N,K]^T (+bias), split-x3: acc += Ah*Bh + Ah*Bl + Al*Bh.
// 1024 threads, warp grid 8(M) x 4(N), warp tile 16x32 (MT=1, NT=4, NP=2).
// Swizzled 64B rows, NSTG-stage cp.async pipeline, single barrier per stage.
__global__ void __launch_bounds__(1024, 1)
hmma_gemm(const __nv_bfloat16* __restrict__ Ah, const __nv_bfloat16* __restrict__ Al, int lda,
          const __nv_bfloat16* __restrict__ Bh, const __nv_bfloat16* __restrict__ Bl, int ldb,
          int K, const float* __restrict__ bias,
          float* __restrict__ C, int N, int ldc) {
    constexpr int NT = 4, NP = 2;
    extern __shared__ char smem[];
    const uint32_t sb = smem_u32(smem);
    const int tid  = threadIdx.x;
    const int lane = tid & 31;
    const int wid  = tid >> 5;
    const int wm   = (wid & 7) * 16;      // 8 warps along M
    const int wn   = (wid >> 3) * 32;     // 4 warps along N
    const long m0  = (long)blockIdx.y * TBM;
    const long n0  = (long)blockIdx.x * BN;

    float acc[NT][4];
#pragma unroll
    for (int j = 0; j < NT; j++)
#pragma unroll
        for (int c = 0; c < 4; c++) acc[j][c] = 0.f;

    // ldsm row/swizzle bases (row fixed per thread)
    const uint32_t arow_l = wm + (lane & 15);
    const uint32_t a_rb   = arow_l * 64;
    const uint32_t a_rx   = (arow_l >> 1) & 3;
    const uint32_t a_cbit = lane >> 4;         // chunk parity within k-half
    uint32_t brow_l[NP], b_rb[NP], b_rx[NP];
#pragma unroll
    for (int np = 0; np < NP; np++) {
        brow_l[np] = wn + np * 16 + ((lane & 7) | ((lane >> 4) << 3));
        b_rb[np] = brow_l[np] * 64;
        b_rx[np] = (brow_l[np] >> 1) & 3;
    }
    const uint32_t b_cbit = (lane >> 3) & 1;

    // loader: 2 granules per thread (one A, one B)
    const int lrow = (tid & 511) >> 2;
    const int lchk = tid & 3;
    const int isLo = tid >> 9;
    const uint32_t l_aoff = swz64(lrow, lchk) + (isLo ? T_AL : 0);
    const uint32_t l_boff = swz64(lrow, lchk) + (isLo ? T_BL : T_BH);
    const __nv_bfloat16* l_asrc = (isLo ? Al : Ah) + (m0 + lrow) * lda + lchk * 8;
    const __nv_bfloat16* l_bsrc = (isLo ? Bl : Bh) + (n0 + lrow) * ldb + lchk * 8;

    auto load_stage = [&](int buf, long kel) {
        uint32_t st = sb + buf * STAGE_B;
        cp16(st + l_aoff, l_asrc + kel);
        cp16(st + l_boff, l_bsrc + kel);
    };

    const int S = K / BK;
#pragma unroll 1
    for (int p = 0; p < NSTG - 1; p++) {
        load_stage(p, (long)p * BK);
        cp_commit();
    }

#pragma unroll 1
    for (int s = 0; s < S; s++) {
        cp_wait<NSTG - 2>();
        __syncthreads();
        if (s + NSTG - 1 < S)
            load_stage((s + NSTG - 1) % NSTG, (long)(s + NSTG - 1) * BK);
        cp_commit();

        uint32_t st = sb + (s % NSTG) * STAGE_B;
#pragma unroll
        for (int kk = 0; kk < 2; kk++) {
            const uint32_t achk = kk * 2 + a_cbit;
            const uint32_t bchk = kk * 2 + b_cbit;
            uint32_t ahr[4], alr[4], bhr[NP][4], blr[NP][4];
            {
                uint32_t ao = a_rb + ((achk ^ a_rx) << 4);
                ldsm4(ahr, st + ao);
                ldsm4(alr, st + T_AL + ao);
            }
#pragma unroll
            for (int np = 0; np < NP; np++) {
                uint32_t bo = b_rb[np] + ((bchk ^ b_rx[np]) << 4);
                ldsm4(bhr[np], st + T_BH + bo);
                ldsm4(blr[np], st + T_BL + bo);
            }
#pragma unroll
            for (int np = 0; np < NP; np++)
#pragma unroll
                for (int j = 0; j < 2; j++) {
                    int nt = np * 2 + j;
                    mma16816(acc[nt], ahr, bhr[np][2 * j], bhr[np][2 * j + 1]);
                    mma16816(acc[nt], ahr, blr[np][2 * j], blr[np][2 * j + 1]);
                    mma16816(acc[nt], alr, bhr[np][2 * j], bhr[np][2 * j + 1]);
                }
        }
    }

    // epilogue
    const int gr = lane >> 2;
    const int gc = (lane & 3) * 2;
    long m = m0 + wm + gr;
#pragma unroll
    for (int nt = 0; nt < NT; nt++) {
        int n = (int)n0 + wn + nt * 8 + gc;
        if (n < N) {
            float b0 = bias ? bias[n] : 0.f;
            float b1 = bias ? bias[n + 1] : 0.f;
            float2 v0 = make_float2(acc[nt][0] + b0, acc[nt][1] + b1);
            float2 v1 = make_float2(acc[nt][2] + b0, acc[nt][3] + b1);
            *reinterpret_cast<float2*>(C + m * ldc + n) = v0;
            *reinterpret_cast<float2*>(C + (m + 8) * ldc + n) = v1;
        }
    }
}

// ---------------------------------------------------------------- attention
__global__ void attn_kernel(const float* __restrict__ boxes,
                            const float* __restrict__ pos_emb) {
    int row  = blockIdx.x * 8 + (threadIdx.x >> 5);
    int lane = threadIdx.x & 31;
    if (row >= NROWS) return;

    const float* region = g_region + (long)row * N1;
    float reg[7];
#pragma unroll
    for (int i = 0; i < 7; i++) {
        int e = lane + 32 * i;
        reg[i] = (e < PEMB) ? region[e] : 0.f;
    }

    const float* brow = boxes + (long)row * (2 * BOXL);
    int   idx[BOXL];
    float w[BOXL], sc[BOXL];
#pragma unroll
    for (int k = 0; k < BOXL; k++) {
        idx[k] = (int)brow[k];
        w[k]   = brow[BOXL + k];
    }

#pragma unroll
    for (int k = 0; k < BOXL; k++) {
        const float* pe = pos_emb + (long)idx[k] * PEMB;
        float p = 0.f;
#pragma unroll
        for (int i = 0; i < 7; i++) {
            int e = lane + 32 * i;
            if (e < PEMB) p += reg[i] * pe[e];
        }
#pragma unroll
        for (int o = 16; o > 0; o >>= 1)
            p += __shfl_xor_sync(0xffffffffu, p, o);
        sc[k] = tanhf(p);
    }

    float mx = -1e30f;
#pragma unroll
    for (int k = 0; k < BOXL; k++) mx = fmaxf(mx, sc[k]);
    float ssum = 0.f;
#pragma unroll
    for (int k = 0; k < BOXL; k++) { sc[k] = expf(sc[k] - mx); ssum += sc[k]; }
    float tot = 0.f;
#pragma unroll
    for (int k = 0; k < BOXL; k++) { sc[k] = sc[k] / ssum * w[k]; tot += sc[k]; }
    float inv = 1.f / (tot + 1e-6f);

#pragma unroll
    for (int i = 0; i < 7; i++) {
        int e = lane + 32 * i;
        if (e < PEMB) {
            float f = 0.f;
#pragma unroll
            for (int k = 0; k < BOXL; k++)
                f += sc[k] * pos_emb[(long)idx[k] * PEMB + e];
            f *= inv;
            __nv_bfloat16 h, l; split2(f, h, l);
            g_Xh[(long)row * K2 + K1 + e] = h;
            g_Xl[(long)row * K2 + K1 + e] = l;
        }
    }
}

// ---------------------------------------------------------------- L2 norm
__global__ void norm_kernel(float* __restrict__ out) {
    int row  = blockIdx.x * 8 + (threadIdx.x >> 5);
    int lane = threadIdx.x & 31;
    if (row >= NROWS) return;

    float4* p = reinterpret_cast<float4*>(out + (long)row * N2);
    float4 v[8];
    float s = 0.f;
#pragma unroll
    for (int i = 0; i < 8; i++) {
        v[i] = p[lane + 32 * i];
        s += v[i].x * v[i].x + v[i].y * v[i].y + v[i].z * v[i].z + v[i].w * v[i].w;
    }
#pragma unroll
    for (int o = 16; o > 0; o >>= 1)
        s += __shfl_xor_sync(0xffffffffu, s, o);
    float scale = 1.f / (sqrtf(s) + 1e-8f);
#pragma unroll
    for (int i = 0; i < 8; i++) {
        v[i].x *= scale; v[i].y *= scale; v[i].z *= scale; v[i].w *= scale;
        p[lane + 32 * i] = v[i];
    }
}

// ---------------------------------------------------------------- launch
extern "C" void kernel_launch(void* const* d_in, const int* in_sizes, int n_in,
                              void* d_out, int out_size) {
    const float* images  = (const float*)d_in[0];
    const float* tag     = (const float*)d_in[1];
    const float* boxes   = (const float*)d_in[2];
    const float* pos_emb = (const float*)d_in[3];
    const float* attn_W  = (const float*)d_in[4];
    const float* fc_W    = (const float*)d_in[5];
    const float* fc_b    = (const float*)d_in[6];
    float* out = (float*)d_out;

    cudaFuncSetAttribute(hmma_gemm, cudaFuncAttributeMaxDynamicSharedMemorySize,
                         SMEM_SZ);

    void *xh, *xl, *w2h, *w2l, *w1h, *w1l, *rg;
    cudaGetSymbolAddress(&xh, g_Xh);   cudaGetSymbolAddress(&xl, g_Xl);
    cudaGetSymbolAddress(&w2h, g_W2h); cudaGetSymbolAddress(&w2l, g_W2l);
    cudaGetSymbolAddress(&w1h, g_W1h); cudaGetSymbolAddress(&w1l, g_W1l);
    cudaGetSymbolAddress(&rg, g_region);

    // 1. conversions
    convX_kernel<<<(NROWS * 768 + 255) / 256, 256>>>(images, tag);
    convW2_kernel<<<(N2 * K2 + 255) / 256, 256>>>(fc_W);
    convW1_kernel<<<(N1P * K1 + 255) / 256, 256>>>(attn_W);

    // 2. GEMM1: region = X[:, :2816] @ attn_W^T  (144 CTAs, 1 wave)
    {
        dim3 grid(N1P / BN, NROWS / TBM);
        hmma_gemm<<<grid, 1024, SMEM_SZ>>>(
            (const __nv_bfloat16*)xh, (const __nv_bfloat16*)xl, K2,
            (const __nv_bfloat16*)w1h, (const __nv_bfloat16*)w1l, K1,
            K1, nullptr, (float*)rg, N1, N1);
    }

    // 3. attention -> box_feat (bf16 split) into X[:, 2816:3016]
    attn_kernel<<<NROWS / 8, 256>>>(boxes, pos_emb);

    // 4. GEMM2: out = X @ W2^T + fc_b
    {
        dim3 grid(N2 / BN, NROWS / TBM);
        hmma_gemm<<<grid, 1024, SMEM_SZ>>>(
            (const __nv_bfloat16*)xh, (const __nv_bfloat16*)xl, K2,
            (const __nv_bfloat16*)w2h, (const __nv_bfloat16*)w2l, K2,
            K2, fc_b, out, N2, N2);
    }

    // 5. L2 normalize
    norm_kernel<<<NROWS / 8, 256>>>(out);
}

// round 9
// speedup vs baseline: 2.6391x; 1.1443x over previous
#include <cuda_runtime.h>
#include <cuda_bf16.h>
#include <math.h>
#include <stdint.h>

// ---------------------------------------------------------------- constants
#define NROWS   9216      // B*R
#define K1      2816      // IMG+TAG
#define K2      3072      // padded (3016 -> 3072)
#define K2RAW   3016
#define N1      200       // POS_EMBED
#define N1P     256       // padded
#define N2      1024
#define BOXL    15
#define PEMB    200

#define BN      128
#define BK      32

// ---------------------------------------------------------------- scratch
__device__ __nv_bfloat16 g_Xh[(long)NROWS * K2];
__device__ __nv_bfloat16 g_Xl[(long)NROWS * K2];
__device__ __nv_bfloat16 g_W2h[(long)N2 * K2];
__device__ __nv_bfloat16 g_W2l[(long)N2 * K2];
__device__ __nv_bfloat16 g_W1h[(long)N1P * K1];
__device__ __nv_bfloat16 g_W1l[(long)N1P * K1];
__device__ float g_region[(long)NROWS * N1];

// ---------------------------------------------------------------- utils
__device__ __forceinline__ uint32_t smem_u32(const void* p) {
    uint32_t a;
    asm("{ .reg .u64 t; cvta.to.shared.u64 t, %1; cvt.u32.u64 %0, t; }"
        : "=r"(a) : "l"(p));
    return a;
}
// Swizzle<2,4,3>: 64B rows, chunk(16B) ^= (row>>1)&3  — conflict-free ldsm/STS
__device__ __forceinline__ uint32_t swz64(uint32_t row, uint32_t chunk) {
    return row * 64 + ((chunk ^ ((row >> 1) & 3)) << 4);
}
__device__ __forceinline__ void cp16(uint32_t dst, const void* src) {
    asm volatile("cp.async.cg.shared.global [%0], [%1], 16;" :: "r"(dst), "l"(src));
}
__device__ __forceinline__ void cp_commit() {
    asm volatile("cp.async.commit_group;" ::: "memory");
}
template<int N>
__device__ __forceinline__ void cp_wait() {
    asm volatile("cp.async.wait_group %0;" :: "n"(N) : "memory");
}
__device__ __forceinline__ void ldsm4(uint32_t* r, uint32_t addr) {
    asm volatile("ldmatrix.sync.aligned.m8n8.x4.shared.b16 {%0,%1,%2,%3}, [%4];"
                 : "=r"(r[0]), "=r"(r[1]), "=r"(r[2]), "=r"(r[3]) : "r"(addr));
}
__device__ __forceinline__ void mma16816(float* d, const uint32_t* a,
                                         uint32_t b0, uint32_t b1) {
    asm volatile(
        "mma.sync.aligned.m16n8k16.row.col.f32.bf16.bf16.f32 "
        "{%0,%1,%2,%3}, {%4,%5,%6,%7}, {%8,%9}, {%0,%1,%2,%3};"
        : "+f"(d[0]), "+f"(d[1]), "+f"(d[2]), "+f"(d[3])
        : "r"(a[0]), "r"(a[1]), "r"(a[2]), "r"(a[3]), "r"(b0), "r"(b1));
}
__device__ __forceinline__ void split2(float v, __nv_bfloat16& h, __nv_bfloat16& l) {
    h = __float2bfloat16(v);
    l = __float2bfloat16(v - __bfloat162float(h));
}

// ---------------------------------------------------------------- conversions
__global__ void convX_kernel(const float* __restrict__ images,
                             const float* __restrict__ tag) {
    int i = blockIdx.x * blockDim.x + threadIdx.x;
    if (i >= NROWS * 768) return;
    int row = i / 768;
    int c4  = i - row * 768;
    float4 v;
    if (c4 < 512)      v = reinterpret_cast<const float4*>(images)[(long)row * 512 + c4];
    else if (c4 < 704) v = reinterpret_cast<const float4*>(tag)[(long)row * 192 + (c4 - 512)];
    else if (c4 < 754) return;   // box_feat region: written by attn kernel
    else               v = make_float4(0.f, 0.f, 0.f, 0.f);
    long base = (long)row * K2 + c4 * 4;
    __nv_bfloat16 h[4], l[4];
    split2(v.x, h[0], l[0]); split2(v.y, h[1], l[1]);
    split2(v.z, h[2], l[2]); split2(v.w, h[3], l[3]);
    *reinterpret_cast<uint2*>(g_Xh + base) = *reinterpret_cast<uint2*>(h);
    *reinterpret_cast<uint2*>(g_Xl + base) = *reinterpret_cast<uint2*>(l);
}

__global__ void convW2_kernel(const float* __restrict__ fcW) {
    int i = blockIdx.x * blockDim.x + threadIdx.x;
    if (i >= N2 * K2) return;
    int n = i / K2;
    int k = i - n * K2;
    float v;
    if (k < 2048)      v = fcW[(long)n * K2RAW + k];
    else if (k < 2816) v = fcW[(long)n * K2RAW + k + 200];
    else if (k < 3016) v = fcW[(long)n * K2RAW + k - 768];
    else               v = 0.f;
    __nv_bfloat16 h, l; split2(v, h, l);
    g_W2h[i] = h; g_W2l[i] = l;
}

__global__ void convW1_kernel(const float* __restrict__ aW) {
    int i = blockIdx.x * blockDim.x + threadIdx.x;
    if (i >= N1P * K1) return;
    int n = i / K1;
    int k = i - n * K1;
    float v = (n < N1) ? aW[(long)n * K1 + k] : 0.f;
    __nv_bfloat16 h, l; split2(v, h, l);
    g_W1h[i] = h; g_W1l[i] = l;
}

// ---------------------------------------------------------------- HMMA GEMM
// C[M,N] = A[M,K]*B[N,K]^T (+bias), split-x3: acc += Ah*Bh + Ah*Bl + Al*Bh.
// Template: TBM rows/CTA, MW x NW warp grid, NTH threads, NSTG stages.
// 64B swizzled rows, single barrier per K-stage.
template<int TBM, int MW, int NW, int NSTG, int NTH>
__global__ void __launch_bounds__(NTH, 1)
hmma_gemm(const __nv_bfloat16* __restrict__ Ah, const __nv_bfloat16* __restrict__ Al, int lda,
          const __nv_bfloat16* __restrict__ Bh, const __nv_bfloat16* __restrict__ Bl, int ldb,
          int K, const float* __restrict__ bias,
          float* __restrict__ C, int N, int ldc) {
    constexpr int MT = (TBM / MW) / 16;
    constexpr int NT = (128 / NW) / 8;
    constexpr int NP = NT / 2;
    constexpr int T_AL = TBM * 64;
    constexpr int T_BH = 2 * TBM * 64;
    constexpr int T_BL = T_BH + BN * 64;
    constexpr int STAGE_B = 2 * (TBM + BN) * 64;
    constexpr int GR_A = TBM * 4;     // granules per A half
    constexpr int GR_B = BN * 4;      // granules per B half
    constexpr int GR_TOT = 2 * GR_A + 2 * GR_B;
    constexpr int LREP = GR_TOT / NTH;

    extern __shared__ char smem[];
    const uint32_t sb = smem_u32(smem);
    const int tid  = threadIdx.x;
    const int lane = tid & 31;
    const int wid  = tid >> 5;
    const int wm   = (wid % MW) * (TBM / MW);
    const int wn   = (wid / MW) * (128 / NW);
    const long m0  = (long)blockIdx.y * TBM;
    const long n0  = (long)blockIdx.x * BN;

    float acc[MT][NT][4];
#pragma unroll
    for (int i = 0; i < MT; i++)
#pragma unroll
        for (int j = 0; j < NT; j++)
#pragma unroll
            for (int c = 0; c < 4; c++) acc[i][j][c] = 0.f;

    // ldsm addressing (64B swizzled rows)
    uint32_t a_rb[MT], a_rx[MT];
#pragma unroll
    for (int mt = 0; mt < MT; mt++) {
        uint32_t r = wm + mt * 16 + (lane & 15);
        a_rb[mt] = r * 64; a_rx[mt] = (r >> 1) & 3;
    }
    const uint32_t a_cbit = lane >> 4;
    uint32_t b_rb[NP], b_rx[NP];
#pragma unroll
    for (int np = 0; np < NP; np++) {
        uint32_t r = wn + np * 16 + ((lane & 7) | ((lane >> 4) << 3));
        b_rb[np] = r * 64; b_rx[np] = (r >> 1) & 3;
    }
    const uint32_t b_cbit = (lane >> 3) & 1;

    auto load_stage = [&](int buf, long kel) {
        uint32_t st = sb + buf * STAGE_B;
#pragma unroll
        for (int i = 0; i < LREP; i++) {
            int g = tid + i * NTH;
            int row = (g >> 2) % TBM;          // works for A sections
            int chunk = g & 3;
            if (g < GR_A) {
                cp16(st + swz64(row, chunk), Ah + (m0 + row) * lda + kel + chunk * 8);
            } else if (g < 2 * GR_A) {
                cp16(st + T_AL + swz64(row, chunk), Al + (m0 + row) * lda + kel + chunk * 8);
            } else if (g < 2 * GR_A + GR_B) {
                int br = (g - 2 * GR_A) >> 2;
                cp16(st + T_BH + swz64(br, chunk), Bh + (n0 + br) * ldb + kel + chunk * 8);
            } else {
                int br = (g - 2 * GR_A - GR_B) >> 2;
                cp16(st + T_BL + swz64(br, chunk), Bl + (n0 + br) * ldb + kel + chunk * 8);
            }
        }
    };

    const int S = K / BK;
#pragma unroll 1
    for (int p = 0; p < NSTG - 1; p++) {
        load_stage(p, (long)p * BK);
        cp_commit();
    }

#pragma unroll 1
    for (int s = 0; s < S; s++) {
        cp_wait<NSTG - 2>();
        __syncthreads();
        if (s + NSTG - 1 < S)
            load_stage((s + NSTG - 1) % NSTG, (long)(s + NSTG - 1) * BK);
        cp_commit();

        uint32_t st = sb + (s % NSTG) * STAGE_B;
#pragma unroll
        for (int kk = 0; kk < 2; kk++) {
            const uint32_t achk = kk * 2 + a_cbit;
            const uint32_t bchk = kk * 2 + b_cbit;
            uint32_t ahr[MT][4], alr[MT][4], bhr[NP][4], blr[NP][4];
#pragma unroll
            for (int mt = 0; mt < MT; mt++) {
                uint32_t ao = a_rb[mt] + ((achk ^ a_rx[mt]) << 4);
                ldsm4(ahr[mt], st + ao);
                ldsm4(alr[mt], st + T_AL + ao);
            }
#pragma unroll
            for (int np = 0; np < NP; np++) {
                uint32_t bo = b_rb[np] + ((bchk ^ b_rx[np]) << 4);
                ldsm4(bhr[np], st + T_BH + bo);
                ldsm4(blr[np], st + T_BL + bo);
            }
#pragma unroll
            for (int np = 0; np < NP; np++)
#pragma unroll
                for (int j = 0; j < 2; j++) {
                    int nt = np * 2 + j;
#pragma unroll
                    for (int mt = 0; mt < MT; mt++) {
                        mma16816(acc[mt][nt], ahr[mt], bhr[np][2*j], bhr[np][2*j+1]);
                        mma16816(acc[mt][nt], ahr[mt], blr[np][2*j], blr[np][2*j+1]);
                        mma16816(acc[mt][nt], alr[mt], bhr[np][2*j], bhr[np][2*j+1]);
                    }
                }
        }
    }

    // epilogue
    const int gr = lane >> 2;
    const int gc = (lane & 3) * 2;
#pragma unroll
    for (int mt = 0; mt < MT; mt++) {
        long m = m0 + wm + mt * 16 + gr;
#pragma unroll
        for (int nt = 0; nt < NT; nt++) {
            int n = (int)n0 + wn + nt * 8 + gc;
            if (n < N) {
                float b0 = bias ? bias[n] : 0.f;
                float b1 = bias ? bias[n + 1] : 0.f;
                float2 v0 = make_float2(acc[mt][nt][0] + b0, acc[mt][nt][1] + b1);
                float2 v1 = make_float2(acc[mt][nt][2] + b0, acc[mt][nt][3] + b1);
                *reinterpret_cast<float2*>(C + m * ldc + n) = v0;
                *reinterpret_cast<float2*>(C + (m + 8) * ldc + n) = v1;
            }
        }
    }
}

// ---------------------------------------------------------------- attention
__global__ void attn_kernel(const float* __restrict__ boxes,
                            const float* __restrict__ pos_emb) {
    int row  = blockIdx.x * 8 + (threadIdx.x >> 5);
    int lane = threadIdx.x & 31;
    if (row >= NROWS) return;

    const float* region = g_region + (long)row * N1;
    float reg[7];
#pragma unroll
    for (int i = 0; i < 7; i++) {
        int e = lane + 32 * i;
        reg[i] = (e < PEMB) ? region[e] : 0.f;
    }

    const float* brow = boxes + (long)row * (2 * BOXL);
    int   idx[BOXL];
    float w[BOXL], sc[BOXL];
#pragma unroll
    for (int k = 0; k < BOXL; k++) {
        idx[k] = (int)brow[k];
        w[k]   = brow[BOXL + k];
    }

#pragma unroll
    for (int k = 0; k < BOXL; k++) {
        const float* pe = pos_emb + (long)idx[k] * PEMB;
        float p = 0.f;
#pragma unroll
        for (int i = 0; i < 7; i++) {
            int e = lane + 32 * i;
            if (e < PEMB) p += reg[i] * pe[e];
        }
#pragma unroll
        for (int o = 16; o > 0; o >>= 1)
            p += __shfl_xor_sync(0xffffffffu, p, o);
        sc[k] = tanhf(p);
    }

    float mx = -1e30f;
#pragma unroll
    for (int k = 0; k < BOXL; k++) mx = fmaxf(mx, sc[k]);
    float ssum = 0.f;
#pragma unroll
    for (int k = 0; k < BOXL; k++) { sc[k] = expf(sc[k] - mx); ssum += sc[k]; }
    float tot = 0.f;
#pragma unroll
    for (int k = 0; k < BOXL; k++) { sc[k] = sc[k] / ssum * w[k]; tot += sc[k]; }
    float inv = 1.f / (tot + 1e-6f);

#pragma unroll
    for (int i = 0; i < 7; i++) {
        int e = lane + 32 * i;
        if (e < PEMB) {
            float f = 0.f;
#pragma unroll
            for (int k = 0; k < BOXL; k++)
                f += sc[k] * pos_emb[(long)idx[k] * PEMB + e];
            f *= inv;
            __nv_bfloat16 h, l; split2(f, h, l);
            g_Xh[(long)row * K2 + K1 + e] = h;
            g_Xl[(long)row * K2 + K1 + e] = l;
        }
    }
}

// ---------------------------------------------------------------- L2 norm
__global__ void norm_kernel(float* __restrict__ out) {
    int row  = blockIdx.x * 8 + (threadIdx.x >> 5);
    int lane = threadIdx.x & 31;
    if (row >= NROWS) return;

    float4* p = reinterpret_cast<float4*>(out + (long)row * N2);
    float4 v[8];
    float s = 0.f;
#pragma unroll
    for (int i = 0; i < 8; i++) {
        v[i] = p[lane + 32 * i];
        s += v[i].x * v[i].x + v[i].y * v[i].y + v[i].z * v[i].z + v[i].w * v[i].w;
    }
#pragma unroll
    for (int o = 16; o > 0; o >>= 1)
        s += __shfl_xor_sync(0xffffffffu, s, o);
    float scale = 1.f / (sqrtf(s) + 1e-8f);
#pragma unroll
    for (int i = 0; i < 8; i++) {
        v[i].x *= scale; v[i].y *= scale; v[i].z *= scale; v[i].w *= scale;
        p[lane + 32 * i] = v[i];
    }
}

// ---------------------------------------------------------------- launch
#define SMEM1 (5 * 2 * (128 + 128) * 64)   // 163840 — GEMM1 (TBM=128, 5 stages)
#define SMEM2 (4 * 2 * (256 + 128) * 64)   // 196608 — GEMM2 (TBM=256, 4 stages)

extern "C" void kernel_launch(void* const* d_in, const int* in_sizes, int n_in,
                              void* d_out, int out_size) {
    const float* images  = (const float*)d_in[0];
    const float* tag     = (const float*)d_in[1];
    const float* boxes   = (const float*)d_in[2];
    const float* pos_emb = (const float*)d_in[3];
    const float* attn_W  = (const float*)d_in[4];
    const float* fc_W    = (const float*)d_in[5];
    const float* fc_b    = (const float*)d_in[6];
    float* out = (float*)d_out;

    cudaFuncSetAttribute(hmma_gemm<128, 8, 4, 5, 1024>,
                         cudaFuncAttributeMaxDynamicSharedMemorySize, SMEM1);
    cudaFuncSetAttribute(hmma_gemm<256, 8, 2, 4, 512>,
                         cudaFuncAttributeMaxDynamicSharedMemorySize, SMEM2);

    void *xh, *xl, *w2h, *w2l, *w1h, *w1l, *rg;
    cudaGetSymbolAddress(&xh, g_Xh);   cudaGetSymbolAddress(&xl, g_Xl);
    cudaGetSymbolAddress(&w2h, g_W2h); cudaGetSymbolAddress(&w2l, g_W2l);
    cudaGetSymbolAddress(&w1h, g_W1h); cudaGetSymbolAddress(&w1l, g_W1l);
    cudaGetSymbolAddress(&rg, g_region);

    // 1. conversions
    convX_kernel<<<(NROWS * 768 + 255) / 256, 256>>>(images, tag);
    convW2_kernel<<<(N2 * K2 + 255) / 256, 256>>>(fc_W);
    convW1_kernel<<<(N1P * K1 + 255) / 256, 256>>>(attn_W);

    // 2. GEMM1: region = X[:, :2816] @ attn_W^T  (144 CTAs, R8 config)
    {
        dim3 grid(N1P / BN, NROWS / 128);
        hmma_gemm<128, 8, 4, 5, 1024><<<grid, 1024, SMEM1>>>(
            (const __nv_bfloat16*)xh, (const __nv_bfloat16*)xl, K2,
            (const __nv_bfloat16*)w1h, (const __nv_bfloat16*)w1l, K1,
            K1, nullptr, (float*)rg, N1, N1);
    }

    // 3. attention -> box_feat (bf16 split) into X[:, 2816:3016]
    attn_kernel<<<NROWS / 8, 256>>>(boxes, pos_emb);

    // 4. GEMM2: out = X @ W2^T + fc_b  (288 CTAs, 32x64 warp tiles, 64B rows)
    {
        dim3 grid(N2 / BN, NROWS / 256);
        hmma_gemm<256, 8, 2, 4, 512><<<grid, 512, SMEM2>>>(
            (const __nv_bfloat16*)xh, (const __nv_bfloat16*)xl, K2,
            (const __nv_bfloat16*)w2h, (const __nv_bfloat16*)w2l, K2,
            K2, fc_b, out, N2, N2);
    }

    // 5. L2 normalize
    norm_kernel<<<NROWS / 8, 256>>>(out);
}

// round 10
// speedup vs baseline: 6.3020x; 2.3879x over previous
#include <cuda_runtime.h>
#include <cuda_fp16.h>
#include <math.h>
#include <stdint.h>

// ---------------------------------------------------------------- constants
#define NROWS   9216      // B*R
#define K1      2816      // IMG+TAG
#define K2      3072      // padded (3016 -> 3072)
#define K2RAW   3016
#define N1      200       // POS_EMBED
#define N1P     256       // padded
#define N2      1024
#define BOXL    15
#define PEMB    200

#define BN      128
#define BK      64        // fp16 K elements per stage (128B per row)

// ---------------------------------------------------------------- scratch
__device__ __half g_Xf[(long)NROWS * K2];
__device__ __half g_W2f[(long)N2 * K2];
__device__ __half g_W1f[(long)N1P * K1];
__device__ float g_region[(long)NROWS * N1];

// ---------------------------------------------------------------- utils
__device__ __forceinline__ uint32_t smem_u32(const void* p) {
    uint32_t a;
    asm("{ .reg .u64 t; cvta.to.shared.u64 t, %1; cvt.u32.u64 %0, t; }"
        : "=r"(a) : "l"(p));
    return a;
}
// SW128 swizzle on 128B rows: chunk(16B) ^= row&7 — conflict-free ldsm/STS
__device__ __forceinline__ uint32_t swz128(uint32_t row, uint32_t chunk) {
    return row * 128 + ((chunk ^ (row & 7)) << 4);
}
__device__ __forceinline__ void cp16(uint32_t dst, const void* src) {
    asm volatile("cp.async.cg.shared.global [%0], [%1], 16;" :: "r"(dst), "l"(src));
}
__device__ __forceinline__ void cp_commit() {
    asm volatile("cp.async.commit_group;" ::: "memory");
}
template<int N>
__device__ __forceinline__ void cp_wait() {
    asm volatile("cp.async.wait_group %0;" :: "n"(N) : "memory");
}
__device__ __forceinline__ void ldsm4(uint32_t* r, uint32_t addr) {
    asm volatile("ldmatrix.sync.aligned.m8n8.x4.shared.b16 {%0,%1,%2,%3}, [%4];"
                 : "=r"(r[0]), "=r"(r[1]), "=r"(r[2]), "=r"(r[3]) : "r"(addr));
}
__device__ __forceinline__ void mma16816(float* d, const uint32_t* a,
                                         uint32_t b0, uint32_t b1) {
    asm volatile(
        "mma.sync.aligned.m16n8k16.row.col.f32.f16.f16.f32 "
        "{%0,%1,%2,%3}, {%4,%5,%6,%7}, {%8,%9}, {%0,%1,%2,%3};"
        : "+f"(d[0]), "+f"(d[1]), "+f"(d[2]), "+f"(d[3])
        : "r"(a[0]), "r"(a[1]), "r"(a[2]), "r"(a[3]), "r"(b0), "r"(b1));
}

// ---------------------------------------------------------------- conversions
// Pack X rows [img | tag | (box later) | 0-pad] as fp16
__global__ void convX_kernel(const float* __restrict__ images,
                             const float* __restrict__ tag) {
    int i = blockIdx.x * blockDim.x + threadIdx.x;
    if (i >= NROWS * 768) return;
    int row = i / 768;
    int c4  = i - row * 768;
    float4 v;
    if (c4 < 512)      v = reinterpret_cast<const float4*>(images)[(long)row * 512 + c4];
    else if (c4 < 704) v = reinterpret_cast<const float4*>(tag)[(long)row * 192 + (c4 - 512)];
    else if (c4 < 754) return;   // box_feat region: written by attn kernel
    else               v = make_float4(0.f, 0.f, 0.f, 0.f);
    __half h[4];
    h[0] = __float2half_rn(v.x); h[1] = __float2half_rn(v.y);
    h[2] = __float2half_rn(v.z); h[3] = __float2half_rn(v.w);
    *reinterpret_cast<uint2*>(g_Xf + (long)row * K2 + c4 * 4) =
        *reinterpret_cast<uint2*>(h);
}

// Permute fc_W [1024,3016] (img|box|tag) -> [1024,3072] (img|tag|box|0), fp16
__global__ void convW2_kernel(const float* __restrict__ fcW) {
    int i = blockIdx.x * blockDim.x + threadIdx.x;
    if (i >= N2 * K2) return;
    int n = i / K2;
    int k = i - n * K2;
    float v;
    if (k < 2048)      v = fcW[(long)n * K2RAW + k];
    else if (k < 2816) v = fcW[(long)n * K2RAW + k + 200];
    else if (k < 3016) v = fcW[(long)n * K2RAW + k - 768];
    else               v = 0.f;
    g_W2f[i] = __float2half_rn(v);
}

__global__ void convW1_kernel(const float* __restrict__ aW) {
    int i = blockIdx.x * blockDim.x + threadIdx.x;
    if (i >= N1P * K1) return;
    int n = i / K1;
    int k = i - n * K1;
    float v = (n < N1) ? aW[(long)n * K1 + k] : 0.f;
    g_W1f[i] = __float2half_rn(v);
}

// ---------------------------------------------------------------- HMMA GEMM (fp16 x1)
// C[M,N] = A[M,K]*B[N,K]^T (+bias), fp16 inputs, fp32 accumulate.
// TBM rows/CTA, MW x NW warp grid, NTH threads, NSTG stages, BK=64,
// SW128-swizzled 128B rows, single barrier per K-stage.
template<int TBM, int MW, int NW, int NSTG, int NTH>
__global__ void __launch_bounds__(NTH, 1)
hmma_gemm(const __half* __restrict__ A, int lda,
          const __half* __restrict__ B, int ldb,
          int K, const float* __restrict__ bias,
          float* __restrict__ C, int N, int ldc) {
    constexpr int MT = (TBM / MW) / 16;
    constexpr int NT = (128 / NW) / 8;
    constexpr int NP = NT / 2;
    constexpr int T_B = TBM * 128;
    constexpr int STAGE_B = (TBM + BN) * 128;
    constexpr int GR_A = TBM * 8;      // 16B granules in A section
    constexpr int GR_TOT = (TBM + BN) * 8;
    constexpr int LREP = GR_TOT / NTH;

    extern __shared__ char smem[];
    const uint32_t sb = smem_u32(smem);
    const int tid  = threadIdx.x;
    const int lane = tid & 31;
    const int wid  = tid >> 5;
    const int wm   = (wid % MW) * (TBM / MW);
    const int wn   = (wid / MW) * (128 / NW);
    const long m0  = (long)blockIdx.y * TBM;
    const long n0  = (long)blockIdx.x * BN;

    float acc[MT][NT][4];
#pragma unroll
    for (int i = 0; i < MT; i++)
#pragma unroll
        for (int j = 0; j < NT; j++)
#pragma unroll
            for (int c = 0; c < 4; c++) acc[i][j][c] = 0.f;

    // ldsm addressing
    uint32_t a_rb[MT], a_rx[MT];
#pragma unroll
    for (int mt = 0; mt < MT; mt++) {
        uint32_t r = wm + mt * 16 + (lane & 15);
        a_rb[mt] = r * 128; a_rx[mt] = r & 7;
    }
    const uint32_t a_cb = lane >> 4;
    uint32_t b_rb[NP], b_rx[NP];
#pragma unroll
    for (int np = 0; np < NP; np++) {
        uint32_t r = wn + np * 16 + ((lane & 7) | ((lane >> 4) << 3));
        b_rb[np] = r * 128; b_rx[np] = r & 7;
    }
    const uint32_t b_cb = (lane >> 3) & 1;

    auto load_stage = [&](int buf, long kel) {
        uint32_t st = sb + buf * STAGE_B;
#pragma unroll
        for (int i = 0; i < LREP; i++) {
            int g = tid + i * NTH;
            int chunk = g & 7;
            if (g < GR_A) {
                int row = g >> 3;
                cp16(st + swz128(row, chunk),
                     A + (m0 + row) * lda + kel + chunk * 8);
            } else {
                int row = (g - GR_A) >> 3;
                cp16(st + T_B + swz128(row, chunk),
                     B + (n0 + row) * ldb + kel + chunk * 8);
            }
        }
    };

    const int S = K / BK;
#pragma unroll 1
    for (int p = 0; p < NSTG - 1; p++) {
        load_stage(p, (long)p * BK);
        cp_commit();
    }

#pragma unroll 1
    for (int s = 0; s < S; s++) {
        cp_wait<NSTG - 2>();
        __syncthreads();
        if (s + NSTG - 1 < S)
            load_stage((s + NSTG - 1) % NSTG, (long)(s + NSTG - 1) * BK);
        cp_commit();

        uint32_t st = sb + (s % NSTG) * STAGE_B;
#pragma unroll
        for (int kk = 0; kk < 4; kk++) {       // 4 k16 halves per 64-K stage
            uint32_t af[MT][4], bf[NP][4];
            const uint32_t ac = kk * 2 + a_cb;
            const uint32_t bc = kk * 2 + b_cb;
#pragma unroll
            for (int mt = 0; mt < MT; mt++)
                ldsm4(af[mt], st + a_rb[mt] + ((ac ^ a_rx[mt]) << 4));
#pragma unroll
            for (int np = 0; np < NP; np++)
                ldsm4(bf[np], st + T_B + b_rb[np] + ((bc ^ b_rx[np]) << 4));
#pragma unroll
            for (int np = 0; np < NP; np++)
#pragma unroll
                for (int j = 0; j < 2; j++)
#pragma unroll
                    for (int mt = 0; mt < MT; mt++)
                        mma16816(acc[mt][np * 2 + j], af[mt],
                                 bf[np][2 * j], bf[np][2 * j + 1]);
        }
    }

    // epilogue
    const int gr = lane >> 2;
    const int gc = (lane & 3) * 2;
#pragma unroll
    for (int mt = 0; mt < MT; mt++) {
        long m = m0 + wm + mt * 16 + gr;
#pragma unroll
        for (int nt = 0; nt < NT; nt++) {
            int n = (int)n0 + wn + nt * 8 + gc;
            if (n < N) {
                float b0 = bias ? bias[n] : 0.f;
                float b1 = bias ? bias[n + 1] : 0.f;
                float2 v0 = make_float2(acc[mt][nt][0] + b0, acc[mt][nt][1] + b1);
                float2 v1 = make_float2(acc[mt][nt][2] + b0, acc[mt][nt][3] + b1);
                *reinterpret_cast<float2*>(C + m * ldc + n) = v0;
                *reinterpret_cast<float2*>(C + (m + 8) * ldc + n) = v1;
            }
        }
    }
}

// ---------------------------------------------------------------- attention
__global__ void attn_kernel(const float* __restrict__ boxes,
                            const float* __restrict__ pos_emb) {
    int row  = blockIdx.x * 8 + (threadIdx.x >> 5);
    int lane = threadIdx.x & 31;
    if (row >= NROWS) return;

    const float* region = g_region + (long)row * N1;
    float reg[7];
#pragma unroll
    for (int i = 0; i < 7; i++) {
        int e = lane + 32 * i;
        reg[i] = (e < PEMB) ? region[e] : 0.f;
    }

    const float* brow = boxes + (long)row * (2 * BOXL);
    int   idx[BOXL];
    float w[BOXL], sc[BOXL];
#pragma unroll
    for (int k = 0; k < BOXL; k++) {
        idx[k] = (int)brow[k];
        w[k]   = brow[BOXL + k];
    }

#pragma unroll
    for (int k = 0; k < BOXL; k++) {
        const float* pe = pos_emb + (long)idx[k] * PEMB;
        float p = 0.f;
#pragma unroll
        for (int i = 0; i < 7; i++) {
            int e = lane + 32 * i;
            if (e < PEMB) p += reg[i] * pe[e];
        }
#pragma unroll
        for (int o = 16; o > 0; o >>= 1)
            p += __shfl_xor_sync(0xffffffffu, p, o);
        sc[k] = tanhf(p);
    }

    float mx = -1e30f;
#pragma unroll
    for (int k = 0; k < BOXL; k++) mx = fmaxf(mx, sc[k]);
    float ssum = 0.f;
#pragma unroll
    for (int k = 0; k < BOXL; k++) { sc[k] = expf(sc[k] - mx); ssum += sc[k]; }
    float tot = 0.f;
#pragma unroll
    for (int k = 0; k < BOXL; k++) { sc[k] = sc[k] / ssum * w[k]; tot += sc[k]; }
    float inv = 1.f / (tot + 1e-6f);

#pragma unroll
    for (int i = 0; i < 7; i++) {
        int e = lane + 32 * i;
        if (e < PEMB) {
            float f = 0.f;
#pragma unroll
            for (int k = 0; k < BOXL; k++)
                f += sc[k] * pos_emb[(long)idx[k] * PEMB + e];
            g_Xf[(long)row * K2 + K1 + e] = __float2half_rn(f * inv);
        }
    }
}

// ---------------------------------------------------------------- L2 norm
__global__ void norm_kernel(float* __restrict__ out) {
    int row  = blockIdx.x * 8 + (threadIdx.x >> 5);
    int lane = threadIdx.x & 31;
    if (row >= NROWS) return;

    float4* p = reinterpret_cast<float4*>(out + (long)row * N2);
    float4 v[8];
    float s = 0.f;
#pragma unroll
    for (int i = 0; i < 8; i++) {
        v[i] = p[lane + 32 * i];
        s += v[i].x * v[i].x + v[i].y * v[i].y + v[i].z * v[i].z + v[i].w * v[i].w;
    }
#pragma unroll
    for (int o = 16; o > 0; o >>= 1)
        s += __shfl_xor_sync(0xffffffffu, s, o);
    float scale = 1.f / (sqrtf(s) + 1e-8f);
#pragma unroll
    for (int i = 0; i < 8; i++) {
        v[i].x *= scale; v[i].y *= scale; v[i].z *= scale; v[i].w *= scale;
        p[lane + 32 * i] = v[i];
    }
}

// ---------------------------------------------------------------- launch
#define SMEM1 (5 * (128 + 128) * 128)   // 163840 — GEMM1 (TBM=128, 5 stages)
#define SMEM2 (4 * (256 + 128) * 128)   // 196608 — GEMM2 (TBM=256, 4 stages)

extern "C" void kernel_launch(void* const* d_in, const int* in_sizes, int n_in,
                              void* d_out, int out_size) {
    const float* images  = (const float*)d_in[0];
    const float* tag     = (const float*)d_in[1];
    const float* boxes   = (const float*)d_in[2];
    const float* pos_emb = (const float*)d_in[3];
    const float* attn_W  = (const float*)d_in[4];
    const float* fc_W    = (const float*)d_in[5];
    const float* fc_b    = (const float*)d_in[6];
    float* out = (float*)d_out;

    cudaFuncSetAttribute(hmma_gemm<128, 4, 4, 5, 512>,
                         cudaFuncAttributeMaxDynamicSharedMemorySize, SMEM1);
    cudaFuncSetAttribute(hmma_gemm<256, 8, 2, 4, 512>,
                         cudaFuncAttributeMaxDynamicSharedMemorySize, SMEM2);

    void *xf, *w2f, *w1f, *rg;
    cudaGetSymbolAddress(&xf, g_Xf);
    cudaGetSymbolAddress(&w2f, g_W2f);
    cudaGetSymbolAddress(&w1f, g_W1f);
    cudaGetSymbolAddress(&rg, g_region);

    // 1. conversions (fp16)
    convX_kernel<<<(NROWS * 768 + 255) / 256, 256>>>(images, tag);
    convW2_kernel<<<(N2 * K2 + 255) / 256, 256>>>(fc_W);
    convW1_kernel<<<(N1P * K1 + 255) / 256, 256>>>(attn_W);

    // 2. GEMM1: region = X[:, :2816] @ attn_W^T  (144 CTAs, 32x32 warp tiles)
    {
        dim3 grid(N1P / BN, NROWS / 128);
        hmma_gemm<128, 4, 4, 5, 512><<<grid, 512, SMEM1>>>(
            (const __half*)xf, K2, (const __half*)w1f, K1,
            K1, nullptr, (float*)rg, N1, N1);
    }

    // 3. attention -> box_feat (fp16) into X[:, 2816:3016]
    attn_kernel<<<NROWS / 8, 256>>>(boxes, pos_emb);

    // 4. GEMM2: out = X @ W2^T + fc_b  (288 CTAs, 32x64 warp tiles)
    {
        dim3 grid(N2 / BN, NROWS / 256);
        hmma_gemm<256, 8, 2, 4, 512><<<grid, 512, SMEM2>>>(
            (const __half*)xf, K2, (const __half*)w2f, K2,
            K2, fc_b, out, N2, N2);
    }

    // 5. L2 normalize
    norm_kernel<<<NROWS / 8, 256>>>(out);
}

// round 11
// speedup vs baseline: 6.3995x; 1.0155x over previous
#include <cuda_runtime.h>
#include <cuda_fp16.h>
#include <math.h>
#include <stdint.h>

// ---------------------------------------------------------------- constants
#define NROWS   9216      // B*R
#define K1      2816      // IMG+TAG
#define K2      3072      // padded (3016 -> 3072)
#define K2RAW   3016
#define N1      200       // POS_EMBED
#define N1P     256       // padded
#define N2      1024
#define BOXL    15
#define PEMB    200

#define BN      128
#define BK      64        // fp16 K elements per stage (128B per row)

// ---------------------------------------------------------------- scratch
__device__ __half g_Xf[(long)NROWS * K2];
__device__ __half g_W2f[(long)N2 * K2];
__device__ __half g_W1f[(long)N1P * K1];
__device__ float g_region[(long)NROWS * N1];

// ---------------------------------------------------------------- utils
__device__ __forceinline__ uint32_t smem_u32(const void* p) {
    uint32_t a;
    asm("{ .reg .u64 t; cvta.to.shared.u64 t, %1; cvt.u32.u64 %0, t; }"
        : "=r"(a) : "l"(p));
    return a;
}
// SW128 swizzle on 128B rows: chunk(16B) ^= row&7 — conflict-free ldsm/STS
__device__ __forceinline__ uint32_t swz128(uint32_t row, uint32_t chunk) {
    return row * 128 + ((chunk ^ (row & 7)) << 4);
}
__device__ __forceinline__ void cp16(uint32_t dst, const void* src) {
    asm volatile("cp.async.cg.shared.global [%0], [%1], 16;" :: "r"(dst), "l"(src));
}
__device__ __forceinline__ void cp_commit() {
    asm volatile("cp.async.commit_group;" ::: "memory");
}
template<int N>
__device__ __forceinline__ void cp_wait() {
    asm volatile("cp.async.wait_group %0;" :: "n"(N) : "memory");
}
__device__ __forceinline__ void ldsm4(uint32_t* r, uint32_t addr) {
    asm volatile("ldmatrix.sync.aligned.m8n8.x4.shared.b16 {%0,%1,%2,%3}, [%4];"
                 : "=r"(r[0]), "=r"(r[1]), "=r"(r[2]), "=r"(r[3]) : "r"(addr));
}
__device__ __forceinline__ void mma16816(float* d, const uint32_t* a,
                                         uint32_t b0, uint32_t b1) {
    asm volatile(
        "mma.sync.aligned.m16n8k16.row.col.f32.f16.f16.f32 "
        "{%0,%1,%2,%3}, {%4,%5,%6,%7}, {%8,%9}, {%0,%1,%2,%3};"
        : "+f"(d[0]), "+f"(d[1]), "+f"(d[2]), "+f"(d[3])
        : "r"(a[0]), "r"(a[1]), "r"(a[2]), "r"(a[3]), "r"(b0), "r"(b1));
}

// ---------------------------------------------------------------- conversions
__global__ void convX_kernel(const float* __restrict__ images,
                             const float* __restrict__ tag) {
    int i = blockIdx.x * blockDim.x + threadIdx.x;
    if (i >= NROWS * 768) return;
    int row = i / 768;
    int c4  = i - row * 768;
    float4 v;
    if (c4 < 512)      v = reinterpret_cast<const float4*>(images)[(long)row * 512 + c4];
    else if (c4 < 704) v = reinterpret_cast<const float4*>(tag)[(long)row * 192 + (c4 - 512)];
    else if (c4 < 754) return;   // box_feat region: written by attn kernel
    else               v = make_float4(0.f, 0.f, 0.f, 0.f);
    __half h[4];
    h[0] = __float2half_rn(v.x); h[1] = __float2half_rn(v.y);
    h[2] = __float2half_rn(v.z); h[3] = __float2half_rn(v.w);
    *reinterpret_cast<uint2*>(g_Xf + (long)row * K2 + c4 * 4) =
        *reinterpret_cast<uint2*>(h);
}

__global__ void convW2_kernel(const float* __restrict__ fcW) {
    int i = blockIdx.x * blockDim.x + threadIdx.x;
    if (i >= N2 * K2) return;
    int n = i / K2;
    int k = i - n * K2;
    float v;
    if (k < 2048)      v = fcW[(long)n * K2RAW + k];
    else if (k < 2816) v = fcW[(long)n * K2RAW + k + 200];
    else if (k < 3016) v = fcW[(long)n * K2RAW + k - 768];
    else               v = 0.f;
    g_W2f[i] = __float2half_rn(v);
}

__global__ void convW1_kernel(const float* __restrict__ aW) {
    int i = blockIdx.x * blockDim.x + threadIdx.x;
    if (i >= N1P * K1) return;
    int n = i / K1;
    int k = i - n * K1;
    float v = (n < N1) ? aW[(long)n * K1 + k] : 0.f;
    g_W1f[i] = __float2half_rn(v);
}

// ---------------------------------------------------------------- HMMA GEMM (fp16)
// C[M,N] = A[M,K]*B[N,K]^T (+bias), fp16 inputs, fp32 accumulate.
// TBM rows/CTA, MW x NW warp grid, NTH threads, NSTG stages, BK=64,
// SW128-swizzled 128B rows, single barrier per K-stage.
template<int TBM, int MW, int NW, int NSTG, int NTH>
__global__ void __launch_bounds__(NTH, 1)
hmma_gemm(const __half* __restrict__ A, int lda,
          const __half* __restrict__ B, int ldb,
          int K, const float* __restrict__ bias,
          float* __restrict__ C, int N, int ldc) {
    constexpr int MT = (TBM / MW) / 16;
    constexpr int NT = (128 / NW) / 8;
    constexpr int NP = NT / 2;
    constexpr int T_B = TBM * 128;
    constexpr int STAGE_B = (TBM + BN) * 128;
    constexpr int GR_A = TBM * 8;
    constexpr int GR_TOT = (TBM + BN) * 8;
    constexpr int LREP = GR_TOT / NTH;

    extern __shared__ char smem[];
    const uint32_t sb = smem_u32(smem);
    const int tid  = threadIdx.x;
    const int lane = tid & 31;
    const int wid  = tid >> 5;
    const int wm   = (wid % MW) * (TBM / MW);
    const int wn   = (wid / MW) * (128 / NW);
    const long m0  = (long)blockIdx.y * TBM;
    const long n0  = (long)blockIdx.x * BN;

    float acc[MT][NT][4];
#pragma unroll
    for (int i = 0; i < MT; i++)
#pragma unroll
        for (int j = 0; j < NT; j++)
#pragma unroll
            for (int c = 0; c < 4; c++) acc[i][j][c] = 0.f;

    uint32_t a_rb[MT], a_rx[MT];
#pragma unroll
    for (int mt = 0; mt < MT; mt++) {
        uint32_t r = wm + mt * 16 + (lane & 15);
        a_rb[mt] = r * 128; a_rx[mt] = r & 7;
    }
    const uint32_t a_cb = lane >> 4;
    uint32_t b_rb[NP], b_rx[NP];
#pragma unroll
    for (int np = 0; np < NP; np++) {
        uint32_t r = wn + np * 16 + ((lane & 7) | ((lane >> 4) << 3));
        b_rb[np] = r * 128; b_rx[np] = r & 7;
    }
    const uint32_t b_cb = (lane >> 3) & 1;

    auto load_stage = [&](int buf, long kel) {
        uint32_t st = sb + buf * STAGE_B;
#pragma unroll
        for (int i = 0; i < LREP; i++) {
            int g = tid + i * NTH;
            int chunk = g & 7;
            if (g < GR_A) {
                int row = g >> 3;
                cp16(st + swz128(row, chunk),
                     A + (m0 + row) * lda + kel + chunk * 8);
            } else {
                int row = (g - GR_A) >> 3;
                cp16(st + T_B + swz128(row, chunk),
                     B + (n0 + row) * ldb + kel + chunk * 8);
            }
        }
    };

    const int S = K / BK;
#pragma unroll 1
    for (int p = 0; p < NSTG - 1; p++) {
        load_stage(p, (long)p * BK);
        cp_commit();
    }

#pragma unroll 1
    for (int s = 0; s < S; s++) {
        cp_wait<NSTG - 2>();
        __syncthreads();
        if (s + NSTG - 1 < S)
            load_stage((s + NSTG - 1) % NSTG, (long)(s + NSTG - 1) * BK);
        cp_commit();

        uint32_t st = sb + (s % NSTG) * STAGE_B;
#pragma unroll
        for (int kk = 0; kk < 4; kk++) {
            uint32_t af[MT][4], bf[NP][4];
            const uint32_t ac = kk * 2 + a_cb;
            const uint32_t bc = kk * 2 + b_cb;
#pragma unroll
            for (int mt = 0; mt < MT; mt++)
                ldsm4(af[mt], st + a_rb[mt] + ((ac ^ a_rx[mt]) << 4));
#pragma unroll
            for (int np = 0; np < NP; np++)
                ldsm4(bf[np], st + T_B + b_rb[np] + ((bc ^ b_rx[np]) << 4));
#pragma unroll
            for (int np = 0; np < NP; np++)
#pragma unroll
                for (int j = 0; j < 2; j++)
#pragma unroll
                    for (int mt = 0; mt < MT; mt++)
                        mma16816(acc[mt][np * 2 + j], af[mt],
                                 bf[np][2 * j], bf[np][2 * j + 1]);
        }
    }

    // epilogue
    const int gr = lane >> 2;
    const int gc = (lane & 3) * 2;
#pragma unroll
    for (int mt = 0; mt < MT; mt++) {
        long m = m0 + wm + mt * 16 + gr;
#pragma unroll
        for (int nt = 0; nt < NT; nt++) {
            int n = (int)n0 + wn + nt * 8 + gc;
            if (n < N) {
                float b0 = bias ? bias[n] : 0.f;
                float b1 = bias ? bias[n + 1] : 0.f;
                float2 v0 = make_float2(acc[mt][nt][0] + b0, acc[mt][nt][1] + b1);
                float2 v1 = make_float2(acc[mt][nt][2] + b0, acc[mt][nt][3] + b1);
                *reinterpret_cast<float2*>(C + m * ldc + n) = v0;
                *reinterpret_cast<float2*>(C + (m + 8) * ldc + n) = v1;
            }
        }
    }
}

// ---------------------------------------------------------------- attention
// One warp per row; k-loops NOT unrolled to keep register count low.
__global__ void __launch_bounds__(128) attn_kernel(const float* __restrict__ boxes,
                                                   const float* __restrict__ pos_emb) {
    int row  = blockIdx.x * 4 + (threadIdx.x >> 5);
    int lane = threadIdx.x & 31;
    if (row >= NROWS) return;

    const float* region = g_region + (long)row * N1;
    float reg[7];
#pragma unroll
    for (int i = 0; i < 7; i++) {
        int e = lane + 32 * i;
        reg[i] = (e < PEMB) ? region[e] : 0.f;
    }

    const float* brow = boxes + (long)row * (2 * BOXL);
    float sc[BOXL];

#pragma unroll 1
    for (int k = 0; k < BOXL; k++) {
        const float* pe = pos_emb + (long)((int)brow[k]) * PEMB;
        float p = 0.f;
#pragma unroll
        for (int i = 0; i < 7; i++) {
            int e = lane + 32 * i;
            if (e < PEMB) p += reg[i] * pe[e];
        }
#pragma unroll
        for (int o = 16; o > 0; o >>= 1)
            p += __shfl_xor_sync(0xffffffffu, p, o);
        sc[k] = tanhf(p);
    }

    float mx = -1e30f;
#pragma unroll
    for (int k = 0; k < BOXL; k++) mx = fmaxf(mx, sc[k]);
    float ssum = 0.f;
#pragma unroll
    for (int k = 0; k < BOXL; k++) { sc[k] = expf(sc[k] - mx); ssum += sc[k]; }
    float tot = 0.f;
#pragma unroll
    for (int k = 0; k < BOXL; k++) { sc[k] = sc[k] / ssum * brow[BOXL + k]; tot += sc[k]; }
    float inv = 1.f / (tot + 1e-6f);

    float f[7];
#pragma unroll
    for (int i = 0; i < 7; i++) f[i] = 0.f;
#pragma unroll 1
    for (int k = 0; k < BOXL; k++) {
        const float* pe = pos_emb + (long)((int)brow[k]) * PEMB;
        float w = sc[k];
#pragma unroll
        for (int i = 0; i < 7; i++) {
            int e = lane + 32 * i;
            if (e < PEMB) f[i] += w * pe[e];
        }
    }
#pragma unroll
    for (int i = 0; i < 7; i++) {
        int e = lane + 32 * i;
        if (e < PEMB)
            g_Xf[(long)row * K2 + K1 + e] = __float2half_rn(f[i] * inv);
    }
}

// ---------------------------------------------------------------- L2 norm
__global__ void norm_kernel(float* __restrict__ out) {
    int row  = blockIdx.x * 8 + (threadIdx.x >> 5);
    int lane = threadIdx.x & 31;
    if (row >= NROWS) return;

    float4* p = reinterpret_cast<float4*>(out + (long)row * N2);
    float4 v[8];
    float s = 0.f;
#pragma unroll
    for (int i = 0; i < 8; i++) {
        v[i] = p[lane + 32 * i];
        s += v[i].x * v[i].x + v[i].y * v[i].y + v[i].z * v[i].z + v[i].w * v[i].w;
    }
#pragma unroll
    for (int o = 16; o > 0; o >>= 1)
        s += __shfl_xor_sync(0xffffffffu, s, o);
    float scale = 1.f / (sqrtf(s) + 1e-8f);
#pragma unroll
    for (int i = 0; i < 8; i++) {
        v[i].x *= scale; v[i].y *= scale; v[i].z *= scale; v[i].w *= scale;
        p[lane + 32 * i] = v[i];
    }
}

// ---------------------------------------------------------------- launch
#define SMEM1 (5 * (128 + 128) * 128)   // 163840 — GEMM1 (TBM=128, 5 stages)
#define SMEM2 (3 * (256 + 128) * 128)   // 147456 — GEMM2 (TBM=256, 3 stages)

extern "C" void kernel_launch(void* const* d_in, const int* in_sizes, int n_in,
                              void* d_out, int out_size) {
    const float* images  = (const float*)d_in[0];
    const float* tag     = (const float*)d_in[1];
    const float* boxes   = (const float*)d_in[2];
    const float* pos_emb = (const float*)d_in[3];
    const float* attn_W  = (const float*)d_in[4];
    const float* fc_W    = (const float*)d_in[5];
    const float* fc_b    = (const float*)d_in[6];
    float* out = (float*)d_out;

    cudaFuncSetAttribute(hmma_gemm<128, 4, 4, 5, 512>,
                         cudaFuncAttributeMaxDynamicSharedMemorySize, SMEM1);
    cudaFuncSetAttribute(hmma_gemm<256, 4, 2, 3, 256>,
                         cudaFuncAttributeMaxDynamicSharedMemorySize, SMEM2);

    void *xf, *w2f, *w1f, *rg;
    cudaGetSymbolAddress(&xf, g_Xf);
    cudaGetSymbolAddress(&w2f, g_W2f);
    cudaGetSymbolAddress(&w1f, g_W1f);
    cudaGetSymbolAddress(&rg, g_region);

    // 1. conversions (fp16)
    convX_kernel<<<(NROWS * 768 + 255) / 256, 256>>>(images, tag);
    convW2_kernel<<<(N2 * K2 + 255) / 256, 256>>>(fc_W);
    convW1_kernel<<<(N1P * K1 + 255) / 256, 256>>>(attn_W);

    // 2. GEMM1: region = X[:, :2816] @ attn_W^T  (144 CTAs, 32x32 warp tiles)
    {
        dim3 grid(N1P / BN, NROWS / 128);
        hmma_gemm<128, 4, 4, 5, 512><<<grid, 512, SMEM1>>>(
            (const __half*)xf, K2, (const __half*)w1f, K1,
            K1, nullptr, (float*)rg, N1, N1);
    }

    // 3. attention -> box_feat (fp16) into X[:, 2816:3016]
    attn_kernel<<<NROWS / 4, 128>>>(boxes, pos_emb);

    // 4. GEMM2: out = X @ W2^T + fc_b  (288 CTAs, 64x64 warp tiles)
    {
        dim3 grid(N2 / BN, NROWS / 256);
        hmma_gemm<256, 4, 2, 3, 256><<<grid, 256, SMEM2>>>(
            (const __half*)xf, K2, (const __half*)w2f, K2,
            K2, fc_b, out, N2, N2);
    }

    // 5. L2 normalize
    norm_kernel<<<NROWS / 8, 256>>>(out);
}

// round 12
// speedup vs baseline: 6.5603x; 1.0251x over previous
#include <cuda_runtime.h>
#include <cuda_fp16.h>
#include <math.h>
#include <stdint.h>

// ---------------------------------------------------------------- constants
#define NROWS   9216      // B*R
#define K1      2816      // IMG+TAG
#define K2      3072      // padded (3016 -> 3072)
#define K2RAW   3016
#define N1      200       // POS_EMBED
#define N1P     256       // padded
#define N2      1024
#define BOXL    15
#define PEMB    200

#define BN      128
#define BK      64        // fp16 K elements per stage (128B per row)

// ---------------------------------------------------------------- scratch
__device__ __half g_Xf[(long)NROWS * K2];
__device__ __half g_W2f[(long)N2 * K2];
__device__ __half g_W1f[(long)N1P * K1];
__device__ float g_region[(long)NROWS * N1];

// ---------------------------------------------------------------- utils
__device__ __forceinline__ uint32_t smem_u32(const void* p) {
    uint32_t a;
    asm("{ .reg .u64 t; cvta.to.shared.u64 t, %1; cvt.u32.u64 %0, t; }"
        : "=r"(a) : "l"(p));
    return a;
}
// SW128 swizzle on 128B rows: chunk(16B) ^= row&7 — conflict-free ldsm/STS
__device__ __forceinline__ uint32_t swz128(uint32_t row, uint32_t chunk) {
    return row * 128 + ((chunk ^ (row & 7)) << 4);
}
__device__ __forceinline__ void cp16(uint32_t dst, const void* src) {
    asm volatile("cp.async.cg.shared.global [%0], [%1], 16;" :: "r"(dst), "l"(src));
}
__device__ __forceinline__ void cp_commit() {
    asm volatile("cp.async.commit_group;" ::: "memory");
}
template<int N>
__device__ __forceinline__ void cp_wait() {
    asm volatile("cp.async.wait_group %0;" :: "n"(N) : "memory");
}
__device__ __forceinline__ void ldsm4(uint32_t* r, uint32_t addr) {
    asm volatile("ldmatrix.sync.aligned.m8n8.x4.shared.b16 {%0,%1,%2,%3}, [%4];"
                 : "=r"(r[0]), "=r"(r[1]), "=r"(r[2]), "=r"(r[3]) : "r"(addr));
}
__device__ __forceinline__ void mma16816(float* d, const uint32_t* a,
                                         uint32_t b0, uint32_t b1) {
    asm volatile(
        "mma.sync.aligned.m16n8k16.row.col.f32.f16.f16.f32 "
        "{%0,%1,%2,%3}, {%4,%5,%6,%7}, {%8,%9}, {%0,%1,%2,%3};"
        : "+f"(d[0]), "+f"(d[1]), "+f"(d[2]), "+f"(d[3])
        : "r"(a[0]), "r"(a[1]), "r"(a[2]), "r"(a[3]), "r"(b0), "r"(b1));
}

// ---------------------------------------------------------------- conversions
__global__ void convX_kernel(const float* __restrict__ images,
                             const float* __restrict__ tag) {
    int i = blockIdx.x * blockDim.x + threadIdx.x;
    if (i >= NROWS * 768) return;
    int row = i / 768;
    int c4  = i - row * 768;
    float4 v;
    if (c4 < 512)      v = reinterpret_cast<const float4*>(images)[(long)row * 512 + c4];
    else if (c4 < 704) v = reinterpret_cast<const float4*>(tag)[(long)row * 192 + (c4 - 512)];
    else if (c4 < 754) return;   // box_feat region: written by attn kernel
    else               v = make_float4(0.f, 0.f, 0.f, 0.f);
    __half h[4];
    h[0] = __float2half_rn(v.x); h[1] = __float2half_rn(v.y);
    h[2] = __float2half_rn(v.z); h[3] = __float2half_rn(v.w);
    *reinterpret_cast<uint2*>(g_Xf + (long)row * K2 + c4 * 4) =
        *reinterpret_cast<uint2*>(h);
}

__global__ void convW2_kernel(const float* __restrict__ fcW) {
    int i = blockIdx.x * blockDim.x + threadIdx.x;
    if (i >= N2 * K2) return;
    int n = i / K2;
    int k = i - n * K2;
    float v;
    if (k < 2048)      v = fcW[(long)n * K2RAW + k];
    else if (k < 2816) v = fcW[(long)n * K2RAW + k + 200];
    else if (k < 3016) v = fcW[(long)n * K2RAW + k - 768];
    else               v = 0.f;
    g_W2f[i] = __float2half_rn(v);
}

__global__ void convW1_kernel(const float* __restrict__ aW) {
    int i = blockIdx.x * blockDim.x + threadIdx.x;
    if (i >= N1P * K1) return;
    int n = i / K1;
    int k = i - n * K1;
    float v = (n < N1) ? aW[(long)n * K1 + k] : 0.f;
    g_W1f[i] = __float2half_rn(v);
}

// ---------------------------------------------------------------- HMMA GEMM (fp16)
// C[M,N] = A[M,K]*B[N,K]^T (+bias), fp16 inputs, fp32 accumulate.
// TBM rows/CTA, MW x NW warp grid, NTH threads, NSTG stages, BK=64,
// SW128-swizzled 128B rows, single barrier per K-stage.
// OCC = min CTAs/SM hint.
template<int TBM, int MW, int NW, int NSTG, int NTH, int OCC>
__global__ void __launch_bounds__(NTH, OCC)
hmma_gemm(const __half* __restrict__ A, int lda,
          const __half* __restrict__ B, int ldb,
          int K, const float* __restrict__ bias,
          float* __restrict__ C, int N, int ldc) {
    constexpr int MT = (TBM / MW) / 16;
    constexpr int NT = (128 / NW) / 8;
    constexpr int NP = NT / 2;
    constexpr int T_B = TBM * 128;
    constexpr int STAGE_B = (TBM + BN) * 128;
    constexpr int GR_A = TBM * 8;
    constexpr int GR_TOT = (TBM + BN) * 8;
    constexpr int LREP = GR_TOT / NTH;

    extern __shared__ char smem[];
    const uint32_t sb = smem_u32(smem);
    const int tid  = threadIdx.x;
    const int lane = tid & 31;
    const int wid  = tid >> 5;
    const int wm   = (wid % MW) * (TBM / MW);
    const int wn   = (wid / MW) * (128 / NW);
    const long m0  = (long)blockIdx.y * TBM;
    const long n0  = (long)blockIdx.x * BN;

    float acc[MT][NT][4];
#pragma unroll
    for (int i = 0; i < MT; i++)
#pragma unroll
        for (int j = 0; j < NT; j++)
#pragma unroll
            for (int c = 0; c < 4; c++) acc[i][j][c] = 0.f;

    uint32_t a_rb[MT], a_rx[MT];
#pragma unroll
    for (int mt = 0; mt < MT; mt++) {
        uint32_t r = wm + mt * 16 + (lane & 15);
        a_rb[mt] = r * 128; a_rx[mt] = r & 7;
    }
    const uint32_t a_cb = lane >> 4;
    uint32_t b_rb[NP], b_rx[NP];
#pragma unroll
    for (int np = 0; np < NP; np++) {
        uint32_t r = wn + np * 16 + ((lane & 7) | ((lane >> 4) << 3));
        b_rb[np] = r * 128; b_rx[np] = r & 7;
    }
    const uint32_t b_cb = (lane >> 3) & 1;

    auto load_stage = [&](int buf, long kel) {
        uint32_t st = sb + buf * STAGE_B;
#pragma unroll
        for (int i = 0; i < LREP; i++) {
            int g = tid + i * NTH;
            int chunk = g & 7;
            if (g < GR_A) {
                int row = g >> 3;
                cp16(st + swz128(row, chunk),
                     A + (m0 + row) * lda + kel + chunk * 8);
            } else {
                int row = (g - GR_A) >> 3;
                cp16(st + T_B + swz128(row, chunk),
                     B + (n0 + row) * ldb + kel + chunk * 8);
            }
        }
    };

    const int S = K / BK;
#pragma unroll 1
    for (int p = 0; p < NSTG - 1; p++) {
        load_stage(p, (long)p * BK);
        cp_commit();
    }

#pragma unroll 1
    for (int s = 0; s < S; s++) {
        cp_wait<NSTG - 2>();
        __syncthreads();
        if (s + NSTG - 1 < S)
            load_stage((s + NSTG - 1) % NSTG, (long)(s + NSTG - 1) * BK);
        cp_commit();

        uint32_t st = sb + (s % NSTG) * STAGE_B;
#pragma unroll
        for (int kk = 0; kk < 4; kk++) {
            uint32_t af[MT][4], bf[NP][4];
            const uint32_t ac = kk * 2 + a_cb;
            const uint32_t bc = kk * 2 + b_cb;
#pragma unroll
            for (int mt = 0; mt < MT; mt++)
                ldsm4(af[mt], st + a_rb[mt] + ((ac ^ a_rx[mt]) << 4));
#pragma unroll
            for (int np = 0; np < NP; np++)
                ldsm4(bf[np], st + T_B + b_rb[np] + ((bc ^ b_rx[np]) << 4));
#pragma unroll
            for (int np = 0; np < NP; np++)
#pragma unroll
                for (int j = 0; j < 2; j++)
#pragma unroll
                    for (int mt = 0; mt < MT; mt++)
                        mma16816(acc[mt][np * 2 + j], af[mt],
                                 bf[np][2 * j], bf[np][2 * j + 1]);
        }
    }

    // epilogue
    const int gr = lane >> 2;
    const int gc = (lane & 3) * 2;
#pragma unroll
    for (int mt = 0; mt < MT; mt++) {
        long m = m0 + wm + mt * 16 + gr;
#pragma unroll
        for (int nt = 0; nt < NT; nt++) {
            int n = (int)n0 + wn + nt * 8 + gc;
            if (n < N) {
                float b0 = bias ? bias[n] : 0.f;
                float b1 = bias ? bias[n + 1] : 0.f;
                float2 v0 = make_float2(acc[mt][nt][0] + b0, acc[mt][nt][1] + b1);
                float2 v1 = make_float2(acc[mt][nt][2] + b0, acc[mt][nt][3] + b1);
                *reinterpret_cast<float2*>(C + m * ldc + n) = v0;
                *reinterpret_cast<float2*>(C + (m + 8) * ldc + n) = v1;
            }
        }
    }
}

// ---------------------------------------------------------------- attention
// One warp per row, fully unrolled (R10 form — no local-memory spill of sc[]).
__global__ void attn_kernel(const float* __restrict__ boxes,
                            const float* __restrict__ pos_emb) {
    int row  = blockIdx.x * 8 + (threadIdx.x >> 5);
    int lane = threadIdx.x & 31;
    if (row >= NROWS) return;

    const float* region = g_region + (long)row * N1;
    float reg[7];
#pragma unroll
    for (int i = 0; i < 7; i++) {
        int e = lane + 32 * i;
        reg[i] = (e < PEMB) ? region[e] : 0.f;
    }

    const float* brow = boxes + (long)row * (2 * BOXL);
    int   idx[BOXL];
    float w[BOXL], sc[BOXL];
#pragma unroll
    for (int k = 0; k < BOXL; k++) {
        idx[k] = (int)brow[k];
        w[k]   = brow[BOXL + k];
    }

#pragma unroll
    for (int k = 0; k < BOXL; k++) {
        const float* pe = pos_emb + (long)idx[k] * PEMB;
        float p = 0.f;
#pragma unroll
        for (int i = 0; i < 7; i++) {
            int e = lane + 32 * i;
            if (e < PEMB) p += reg[i] * pe[e];
        }
#pragma unroll
        for (int o = 16; o > 0; o >>= 1)
            p += __shfl_xor_sync(0xffffffffu, p, o);
        sc[k] = tanhf(p);
    }

    float mx = -1e30f;
#pragma unroll
    for (int k = 0; k < BOXL; k++) mx = fmaxf(mx, sc[k]);
    float ssum = 0.f;
#pragma unroll
    for (int k = 0; k < BOXL; k++) { sc[k] = expf(sc[k] - mx); ssum += sc[k]; }
    float tot = 0.f;
#pragma unroll
    for (int k = 0; k < BOXL; k++) { sc[k] = sc[k] / ssum * w[k]; tot += sc[k]; }
    float inv = 1.f / (tot + 1e-6f);

#pragma unroll
    for (int i = 0; i < 7; i++) {
        int e = lane + 32 * i;
        if (e < PEMB) {
            float f = 0.f;
#pragma unroll
            for (int k = 0; k < BOXL; k++)
                f += sc[k] * pos_emb[(long)idx[k] * PEMB + e];
            g_Xf[(long)row * K2 + K1 + e] = __float2half_rn(f * inv);
        }
    }
}

// ---------------------------------------------------------------- L2 norm
__global__ void norm_kernel(float* __restrict__ out) {
    int row  = blockIdx.x * 8 + (threadIdx.x >> 5);
    int lane = threadIdx.x & 31;
    if (row >= NROWS) return;

    float4* p = reinterpret_cast<float4*>(out + (long)row * N2);
    float4 v[8];
    float s = 0.f;
#pragma unroll
    for (int i = 0; i < 8; i++) {
        v[i] = p[lane + 32 * i];
        s += v[i].x * v[i].x + v[i].y * v[i].y + v[i].z * v[i].z + v[i].w * v[i].w;
    }
#pragma unroll
    for (int o = 16; o > 0; o >>= 1)
        s += __shfl_xor_sync(0xffffffffu, s, o);
    float scale = 1.f / (sqrtf(s) + 1e-8f);
#pragma unroll
    for (int i = 0; i < 8; i++) {
        v[i].x *= scale; v[i].y *= scale; v[i].z *= scale; v[i].w *= scale;
        p[lane + 32 * i] = v[i];
    }
}

// ---------------------------------------------------------------- launch
#define SMEM1 (5 * (128 + 128) * 128)   // 163840 — GEMM1 (TBM=128, 5 stages)
#define SMEM2 (3 * (128 + 128) * 128)   //  98304 — GEMM2 (TBM=128, 3 stages, 2 CTA/SM)

extern "C" void kernel_launch(void* const* d_in, const int* in_sizes, int n_in,
                              void* d_out, int out_size) {
    const float* images  = (const float*)d_in[0];
    const float* tag     = (const float*)d_in[1];
    const float* boxes   = (const float*)d_in[2];
    const float* pos_emb = (const float*)d_in[3];
    const float* attn_W  = (const float*)d_in[4];
    const float* fc_W    = (const float*)d_in[5];
    const float* fc_b    = (const float*)d_in[6];
    float* out = (float*)d_out;

    cudaFuncSetAttribute(hmma_gemm<128, 2, 4, 5, 256, 1>,
                         cudaFuncAttributeMaxDynamicSharedMemorySize, SMEM1);
    cudaFuncSetAttribute(hmma_gemm<128, 2, 2, 3, 128, 2>,
                         cudaFuncAttributeMaxDynamicSharedMemorySize, SMEM2);

    void *xf, *w2f, *w1f, *rg;
    cudaGetSymbolAddress(&xf, g_Xf);
    cudaGetSymbolAddress(&w2f, g_W2f);
    cudaGetSymbolAddress(&w1f, g_W1f);
    cudaGetSymbolAddress(&rg, g_region);

    // 1. conversions (fp16)
    convX_kernel<<<(NROWS * 768 + 255) / 256, 256>>>(images, tag);
    convW2_kernel<<<(N2 * K2 + 255) / 256, 256>>>(fc_W);
    convW1_kernel<<<(N1P * K1 + 255) / 256, 256>>>(attn_W);

    // 2. GEMM1: region = X[:, :2816] @ attn_W^T  (144 CTAs, 64x32 warp tiles)
    {
        dim3 grid(N1P / BN, NROWS / 128);
        hmma_gemm<128, 2, 4, 5, 256, 1><<<grid, 256, SMEM1>>>(
            (const __half*)xf, K2, (const __half*)w1f, K1,
            K1, nullptr, (float*)rg, N1, N1);
    }

    // 3. attention -> box_feat (fp16) into X[:, 2816:3016]
    attn_kernel<<<NROWS / 8, 256>>>(boxes, pos_emb);

    // 4. GEMM2: out = X @ W2^T + fc_b  (576 CTAs, 64x64 warp tiles, 2 CTA/SM)
    {
        dim3 grid(N2 / BN, NROWS / 128);
        hmma_gemm<128, 2, 2, 3, 128, 2><<<grid, 128, SMEM2>>>(
            (const __half*)xf, K2, (const __half*)w2f, K2,
            K2, fc_b, out, N2, N2);
    }

    // 5. L2 normalize
    norm_kernel<<<NROWS / 8, 256>>>(out);
}